// round 6
// baseline (speedup 1.0000x reference)
#include <cuda_runtime.h>
#include <math.h>

#define TOKV 21760   // per-view feature tokens: 4*(4096+1024+256+64)

__constant__ int c_N[4]   = {4096, 1024, 256, 64};
__constant__ int c_off[4] = {0, 16384, 20480, 21504};
// 8 cross-attn split slots: level, split index, chunk size
__constant__ int c_sl[8] = {0,0,0,0,1,1,2,3};
__constant__ int c_sk[8] = {0,1,2,3,0,1,0,0};
__constant__ int c_ck[8] = {1024,1024,1024,1024,512,512,256,64};
__constant__ int c_S[4]  = {4,2,1,1};
__constant__ int c_s0[4] = {0,4,6,7};

// single scratch arena (allocations are forbidden)
__device__ float g_buf[40559360];

struct FeatPtrs { const float* p[8]; };

// ---------------- reductions ----------------
__device__ __forceinline__ float warpSum(float v){
#pragma unroll
    for (int o = 16; o > 0; o >>= 1) v += __shfl_xor_sync(0xffffffffu, v, o);
    return v;
}
__device__ __forceinline__ float warpMax(float v){
#pragma unroll
    for (int o = 16; o > 0; o >>= 1) v = fmaxf(v, __shfl_xor_sync(0xffffffffu, v, o));
    return v;
}
__device__ __forceinline__ float blockSum(float v, float* sh){
    int lane = threadIdx.x & 31, w = threadIdx.x >> 5;
    int nw = blockDim.x >> 5;
    __syncthreads();
    v = warpSum(v);
    if (lane == 0) sh[w] = v;
    __syncthreads();
    if (w == 0){
        float r = (threadIdx.x < nw) ? sh[threadIdx.x] : 0.f;
        r = warpSum(r);
        if (lane == 0) sh[0] = r;
    }
    __syncthreads();
    return sh[0];
}
__device__ __forceinline__ float blockMax(float v, float* sh){
    int lane = threadIdx.x & 31, w = threadIdx.x >> 5;
    int nw = blockDim.x >> 5;
    __syncthreads();
    v = warpMax(v);
    if (lane == 0) sh[w] = v;
    __syncthreads();
    if (w == 0){
        float r = (threadIdx.x < nw) ? sh[threadIdx.x] : -1e30f;
        r = warpMax(r);
        if (lane == 0) sh[0] = r;
    }
    __syncthreads();
    return sh[0];
}

// ---------------- one-time: tokenize + LN normalization (affine folded into GEMMs) ----
__global__ void __launch_bounds__(256) k_tok_ln(FeatPtrs fp, float* __restrict__ xhat){
    __shared__ float sh[32];
    int r = blockIdx.x;                 // token row within view
    int v = blockIdx.y;                 // view
    int l = (r < 16384) ? 0 : (r < 20480) ? 1 : (r < 21504) ? 2 : 3;
    int off = c_off[l], Nl = c_N[l];
    int b = (r - off) / Nl, t = (r - off) % Nl;
    const float* f = fp.p[v*4 + l];
    int c = threadIdx.x;
    float x = f[((size_t)(b*256 + c))*Nl + t];
    float m = blockSum(x, sh) * (1.f/256.f);
    float d = x - m;
    float var = blockSum(d*d, sh) * (1.f/256.f);
    xhat[((size_t)v*TOKV + r)*256 + c] = d * rsqrtf(var + 1e-5f);
}

__global__ void k_init_q(const float* __restrict__ qe, float* __restrict__ q){
    int row = blockIdx.x, c = threadIdx.x;
    q[(size_t)row*256 + c] = qe[(row % 100)*256 + c];
}

// -------- SGEMM: C[M,N] = op(A)[M,256] @ W[256,N] (+bias). op: a*gv[k]+bv[k] if gv. ----
__global__ void __launch_bounds__(256) k_gemm(
    const float* __restrict__ A, const float* __restrict__ W,
    const float* __restrict__ gv, const float* __restrict__ bv,
    const float* __restrict__ bias, float* __restrict__ Cout,
    int M, int N)
{
    __shared__ __align__(16) float As[8][128];
    __shared__ __align__(16) float Bs[8][128];
    int tid = threadIdx.x;
    int m0 = blockIdx.x * 128, n0 = blockIdx.y * 128;
    int arow = tid >> 1, acol = (tid & 1) * 4;
    int brow = tid >> 5, bcol = (tid & 31) * 4;
    int tx = tid & 15, ty = tid >> 4;
    float acc[8][8];
#pragma unroll
    for (int i = 0; i < 8; i++)
#pragma unroll
        for (int j = 0; j < 8; j++) acc[i][j] = 0.f;

    const bool pre = (gv != nullptr);
    for (int k0 = 0; k0 < 256; k0 += 8){
        float4 av = make_float4(0.f,0.f,0.f,0.f);
        int gm = m0 + arow;
        if (gm < M) av = *reinterpret_cast<const float4*>(A + (size_t)gm*256 + k0 + acol);
        if (pre){
            float4 gg = *reinterpret_cast<const float4*>(gv + k0 + acol);
            float4 bb = *reinterpret_cast<const float4*>(bv + k0 + acol);
            av.x = fmaf(av.x, gg.x, bb.x); av.y = fmaf(av.y, gg.y, bb.y);
            av.z = fmaf(av.z, gg.z, bb.z); av.w = fmaf(av.w, gg.w, bb.w);
        }
        As[acol+0][arow] = av.x; As[acol+1][arow] = av.y;
        As[acol+2][arow] = av.z; As[acol+3][arow] = av.w;
        *reinterpret_cast<float4*>(&Bs[brow][bcol]) =
            *reinterpret_cast<const float4*>(W + (size_t)(k0 + brow)*N + n0 + bcol);
        __syncthreads();
#pragma unroll
        for (int kk = 0; kk < 8; kk++){
            float a[8], b[8];
            *reinterpret_cast<float4*>(a)     = *reinterpret_cast<float4*>(&As[kk][ty*8]);
            *reinterpret_cast<float4*>(a + 4) = *reinterpret_cast<float4*>(&As[kk][ty*8 + 4]);
            *reinterpret_cast<float4*>(b)     = *reinterpret_cast<float4*>(&Bs[kk][tx*8]);
            *reinterpret_cast<float4*>(b + 4) = *reinterpret_cast<float4*>(&Bs[kk][tx*8 + 4]);
#pragma unroll
            for (int i = 0; i < 8; i++)
#pragma unroll
                for (int j = 0; j < 8; j++) acc[i][j] = fmaf(a[i], b[j], acc[i][j]);
        }
        __syncthreads();
    }
#pragma unroll
    for (int i = 0; i < 8; i++){
        int gm = m0 + ty*8 + i;
        if (gm < M){
#pragma unroll
            for (int j = 0; j < 8; j += 4){
                int gn = n0 + tx*8 + j;
                float4 o;
                o.x = acc[i][j+0]; o.y = acc[i][j+1]; o.z = acc[i][j+2]; o.w = acc[i][j+3];
                if (bias){
                    o.x += bias[gn+0]; o.y += bias[gn+1];
                    o.z += bias[gn+2]; o.w += bias[gn+3];
                }
                *reinterpret_cast<float4*>(Cout + (size_t)gm*N + gn) = o;
            }
        }
    }
}

// ---------------- self-attention over 100 keys, per (h, b, l) ----------------
__global__ void __launch_bounds__(128) k_sa(const float* __restrict__ qkv,
                                            float* __restrict__ osa){
    __shared__ float sK[100][32];
    __shared__ float sV[100][32];
    int h = blockIdx.x, b = blockIdx.y, l = blockIdx.z;
    int lb = l*4 + b;
    const float* qb = qkv + (size_t)lb*100*768;
    for (int idx = threadIdx.x; idx < 3200; idx += 128){
        int j = idx >> 5, c = idx & 31;
        sK[j][c] = qb[(size_t)j*768 + 256 + h*32 + c];
        sV[j][c] = qb[(size_t)j*768 + 512 + h*32 + c];
    }
    __syncthreads();
    int i = threadIdx.x;
    if (i < 100){
        float Q[32];
#pragma unroll
        for (int c = 0; c < 32; c++) Q[c] = qb[(size_t)i*768 + h*32 + c];
        float m = -1e30f, s = 0.f, acc[32];
#pragma unroll
        for (int c = 0; c < 32; c++) acc[c] = 0.f;
        for (int j = 0; j < 100; j++){
            float d = 0.f;
#pragma unroll
            for (int c = 0; c < 32; c++) d = fmaf(Q[c], sK[j][c], d);
            d *= 0.17677669529663687f;
            if (d > m){
                float f = __expf(m - d);
                m = d; s = fmaf(s, f, 1.f);
#pragma unroll
                for (int c = 0; c < 32; c++) acc[c] = fmaf(acc[c], f, sV[j][c]);
            } else {
                float p = __expf(d - m);
                s += p;
#pragma unroll
                for (int c = 0; c < 32; c++) acc[c] = fmaf(p, sV[j][c], acc[c]);
            }
        }
        float inv = 1.f / s;
        float* o = osa + (size_t)(lb*100 + i)*256 + h*32;
#pragma unroll
        for (int c = 0; c < 32; c++) o[c] = acc[c]*inv;
    }
}

// ---------------- row LN (normalization only) ----------------
__global__ void __launch_bounds__(256) k_ln_rows(const float* __restrict__ in,
                                                 float* __restrict__ out){
    __shared__ float sh[32];
    int row = blockIdx.x, c = threadIdx.x;
    float x = in[(size_t)row*256 + c];
    float m = blockSum(x, sh) * (1.f/256.f);
    float d = x - m;
    float var = blockSum(d*d, sh) * (1.f/256.f);
    out[(size_t)row*256 + c] = d * rsqrtf(var + 1e-5f);
}

// ---------------- cross-attention flash partials ----------------
__global__ void __launch_bounds__(128) k_cross(
    const float* __restrict__ qn, const float* __restrict__ Kg,
    const float* __restrict__ Vg, float* __restrict__ pm,
    float* __restrict__ ps, float* __restrict__ pacc)
{
    __shared__ float sK[64][32];
    __shared__ float sV[64][32];
    int ss = blockIdx.x, h = blockIdx.y, vb = blockIdx.z;
    int v = vb >> 2, b = vb & 3;
    int l = c_sl[ss];
    int Nl = c_N[l];
    int ck = c_ck[ss];
    int kbeg = c_sk[ss]*ck;
    int lb = l*4 + b;
    size_t kvbase = ((size_t)v*TOKV + c_off[l] + (size_t)b*Nl)*256 + h*32;
    const float* Kp = Kg + kvbase;
    const float* Vp = Vg + kvbase;
    int i = threadIdx.x;
    float Q[32];
    if (i < 100){
        const float* qp = qn + (size_t)(lb*100 + i)*256 + h*32;
#pragma unroll
        for (int c = 0; c < 32; c++) Q[c] = qp[c];
    }
    float m = -1e30f, s = 0.f, acc[32];
#pragma unroll
    for (int c = 0; c < 32; c++) acc[c] = 0.f;
    for (int kc = kbeg; kc < kbeg + ck; kc += 64){
        __syncthreads();
        for (int idx = threadIdx.x; idx < 2048; idx += 128){
            int j = idx >> 5, c = idx & 31;
            sK[j][c] = Kp[(size_t)(kc + j)*256 + c];
            sV[j][c] = Vp[(size_t)(kc + j)*256 + c];
        }
        __syncthreads();
        if (i < 100){
            for (int j = 0; j < 64; j++){
                float d = 0.f;
#pragma unroll
                for (int c = 0; c < 32; c++) d = fmaf(Q[c], sK[j][c], d);
                d *= 0.17677669529663687f;
                if (d > m){
                    float f = __expf(m - d);
                    m = d; s = fmaf(s, f, 1.f);
#pragma unroll
                    for (int c = 0; c < 32; c++) acc[c] = fmaf(acc[c], f, sV[j][c]);
                } else {
                    float p = __expf(d - m);
                    s += p;
#pragma unroll
                    for (int c = 0; c < 32; c++) acc[c] = fmaf(p, sV[j][c], acc[c]);
                }
            }
        }
    }
    if (i < 100){
        int slot = (vb*8 + h)*8 + ss;
        pm[slot*100 + i] = m;
        ps[slot*100 + i] = s;
        float* pa = pacc + (size_t)(slot*100 + i)*32;
#pragma unroll
        for (int c = 0; c < 32; c++) pa[c] = acc[c];
    }
}

__global__ void __launch_bounds__(128) k_combine(
    const float* __restrict__ pm, const float* __restrict__ ps,
    const float* __restrict__ pacc, float* __restrict__ ocr)
{
    int l = blockIdx.x, h = blockIdx.y, vb = blockIdx.z;
    int i = threadIdx.x;
    if (i >= 100) return;
    int S = c_S[l], s0 = c_s0[l];
    int base = (vb*8 + h)*8 + s0;
    float M = -1e30f;
    for (int k = 0; k < S; k++) M = fmaxf(M, pm[(base + k)*100 + i]);
    float Ss = 0.f, acc[32];
#pragma unroll
    for (int c = 0; c < 32; c++) acc[c] = 0.f;
    for (int k = 0; k < S; k++){
        int slot = base + k;
        float f = __expf(pm[slot*100 + i] - M);
        Ss = fmaf(ps[slot*100 + i], f, Ss);
        const float* pa = pacc + (size_t)(slot*100 + i)*32;
#pragma unroll
        for (int c = 0; c < 32; c++) acc[c] = fmaf(pa[c], f, acc[c]);
    }
    float inv = 1.f / Ss;
    int v = vb >> 2, b = vb & 3;
    int lb = l*4 + b;
    float* o = ocr + (size_t)v*409600 + (size_t)(lb*100 + i)*256 + h*32;
#pragma unroll
    for (int c = 0; c < 32; c++) o[c] = acc[c]*inv;
}

// ---------------- matching score ms = q1 @ q2^T per lb ----------------
__global__ void __launch_bounds__(256) k_match(const float* __restrict__ q12,
                                               float* __restrict__ ms){
    __shared__ float sA[100][33];
    __shared__ float sB[100][33];
    int lb = blockIdx.x;
    int tx = threadIdx.x & 15, ty = threadIdx.x >> 4;
    const float* q1 = q12 + (size_t)lb*25600;
    const float* q2 = q12 + 409600 + (size_t)lb*25600;
    float acc[7][7];
#pragma unroll
    for (int a = 0; a < 7; a++)
#pragma unroll
        for (int bq = 0; bq < 7; bq++) acc[a][bq] = 0.f;
    for (int k0 = 0; k0 < 256; k0 += 32){
        __syncthreads();
        for (int idx = threadIdx.x; idx < 3200; idx += 256){
            int r = idx >> 5, kk = idx & 31;
            sA[r][kk] = q1[(size_t)r*256 + k0 + kk];
            sB[r][kk] = q2[(size_t)r*256 + k0 + kk];
        }
        __syncthreads();
        for (int kk = 0; kk < 32; kk++){
            float a[7], b[7];
#pragma unroll
            for (int ii = 0; ii < 7; ii++){
                int i = ty + 16*ii;
                a[ii] = (i < 100) ? sA[i][kk] : 0.f;
            }
#pragma unroll
            for (int jj = 0; jj < 7; jj++){
                int j = tx + 16*jj;
                b[jj] = (j < 100) ? sB[j][kk] : 0.f;
            }
#pragma unroll
            for (int ii = 0; ii < 7; ii++)
#pragma unroll
                for (int jj = 0; jj < 7; jj++) acc[ii][jj] = fmaf(a[ii], b[jj], acc[ii][jj]);
        }
    }
#pragma unroll
    for (int ii = 0; ii < 7; ii++){
        int i = ty + 16*ii;
        if (i < 100){
#pragma unroll
            for (int jj = 0; jj < 7; jj++){
                int j = tx + 16*jj;
                if (j < 100) ms[(size_t)lb*10000 + i*100 + j] = acc[ii][jj];
            }
        }
    }
}

// ---------------- row (mode 0) / column (mode 1) softmax of ms ----------------
__global__ void __launch_bounds__(128) k_softmax_ms(const float* __restrict__ ms,
                                                    float* __restrict__ wr,
                                                    float* __restrict__ wc){
    __shared__ float sh[32];
    int x = blockIdx.x, lb = blockIdx.y, mode = blockIdx.z;
    int t = threadIdx.x;
    const float* base = ms + (size_t)lb*10000;
    int idx = (mode == 0) ? (x*100 + t) : (t*100 + x);
    float v = (t < 100) ? base[idx] : -1e30f;
    float M = blockMax(v, sh);
    float p = (t < 100) ? __expf(v - M) : 0.f;
    float S = blockSum(p, sh);
    if (t < 100){
        float w = p / S;
        if (mode == 0) wr[(size_t)lb*10000 + x*100 + t] = w;
        else           wc[(size_t)lb*10000 + t*100 + x] = w;
    }
}

// -------- fuse: t[i] = qsa[i]+q1[i]+q2[i]+Σ wr[i][j]q2[j]+Σ wc[j][i]q1[j]; softmax over c
__global__ void __launch_bounds__(256) k_fuse(
    const float* __restrict__ qsa, const float* __restrict__ q12,
    const float* __restrict__ wr, const float* __restrict__ wc,
    float* __restrict__ outp)
{
    __shared__ float swr[100];
    __shared__ float swc[100];
    __shared__ float sh[32];
    int i = blockIdx.x, lb = blockIdx.y, c = threadIdx.x;
    const float* q1 = q12 + (size_t)lb*25600;
    const float* q2 = q12 + 409600 + (size_t)lb*25600;
    if (c < 100){
        swr[c] = wr[(size_t)lb*10000 + i*100 + c];   // wr[i][c]
        swc[c] = wc[(size_t)lb*10000 + c*100 + i];   // wc[c][i]
    }
    __syncthreads();
    float acc = qsa[(size_t)(lb*100 + i)*256 + c] + q1[(size_t)i*256 + c] + q2[(size_t)i*256 + c];
    for (int j = 0; j < 100; j++){
        acc = fmaf(swr[j], q2[(size_t)j*256 + c], acc);
        acc = fmaf(swc[j], q1[(size_t)j*256 + c], acc);
    }
    float M = blockMax(acc, sh);
    float e = __expf(acc - M);
    float S = blockSum(e, sh);
    outp[(size_t)(lb*100 + i)*256 + c] = e / S;
}

// ---------------- host ----------------
extern "C" void kernel_launch(void* const* d_in, const int* in_sizes, int n_in,
                              void* d_out, int out_size)
{
    float* base;
    cudaGetSymbolAddress((void**)&base, g_buf);
    float* xhat = base;                     // 11,141,120
    float* Kb   = base + 11141120;          // 11,141,120
    float* Vb   = base + 22282240;          // 11,141,120
    float* q    = base + 33423360;          // 409,600
    float* qkv  = base + 33832960;          // 1,228,800
    float* osa  = base + 35061760;          // 409,600
    float* qsa  = base + 35471360;          // 409,600
    float* qln  = base + 35880960;          // 409,600
    float* qn   = base + 36290560;          // 409,600
    float* ocr  = base + 36700160;          // 819,200
    float* q12  = base + 37519360;          // 819,200
    float* ms   = base + 38338560;          // 160,000
    float* wr   = base + 38498560;          // 160,000
    float* wc   = base + 38658560;          // 160,000
    float* pm   = base + 38818560;          // 51,200
    float* ps   = base + 38869760;          // 51,200
    float* pacc = base + 38920960;          // 1,638,400

    FeatPtrs fp;
    for (int i = 0; i < 8; i++) fp.p[i] = (const float*)d_in[i];
    const float* qe   = (const float*)d_in[8];
    const float* ng   = (const float*)d_in[9];
    const float* nb   = (const float*)d_in[10];
    const float* wq   = (const float*)d_in[11];
    const float* wk   = (const float*)d_in[12];
    const float* wv   = (const float*)d_in[13];
    const float* wp   = (const float*)d_in[14];
    const float* bp   = (const float*)d_in[15];
    const float* wqkv = (const float*)d_in[16];
    const float* swp  = (const float*)d_in[17];
    const float* sbp  = (const float*)d_in[18];

    k_tok_ln<<<dim3(TOKV, 2), 256>>>(fp, xhat);
    k_init_q<<<1600, 256>>>(qe, q);

    for (int d = 0; d < 6; d++){
        const float* g = ng + d*256;
        const float* b = nb + d*256;
        k_gemm<<<dim3(13, 6), 256>>>(q, wqkv + (size_t)d*256*768,
                                     nullptr, nullptr, nullptr, qkv, 1600, 768);
        k_sa<<<dim3(8, 4, 4), 128>>>(qkv, osa);
        k_gemm<<<dim3(13, 2), 256>>>(osa, swp + (size_t)d*65536,
                                     nullptr, nullptr, sbp + d*256, qsa, 1600, 256);
        k_ln_rows<<<1600, 256>>>(qsa, qln);
        k_gemm<<<dim3(13, 2), 256>>>(qln, wq + (size_t)d*65536,
                                     g, b, nullptr, qn, 1600, 256);
        k_gemm<<<dim3(340, 2), 256>>>(xhat, wk + (size_t)d*65536,
                                      g, b, nullptr, Kb, 43520, 256);
        k_gemm<<<dim3(340, 2), 256>>>(xhat, wv + (size_t)d*65536,
                                      g, b, nullptr, Vb, 43520, 256);
        k_cross<<<dim3(8, 8, 8), 128>>>(qn, Kb, Vb, pm, ps, pacc);
        k_combine<<<dim3(4, 8, 8), 128>>>(pm, ps, pacc, ocr);
        k_gemm<<<dim3(25, 2), 256>>>(ocr, wp + (size_t)d*65536,
                                     nullptr, nullptr, bp + d*256, q12, 3200, 256);
        k_match<<<16, 256>>>(q12, ms);
        k_softmax_ms<<<dim3(100, 16, 2), 128>>>(ms, wr, wc);
        k_fuse<<<dim3(100, 16), 256>>>(qsa, q12, wr, wc,
                                       (d == 5) ? (float*)d_out : q);
    }
}

// round 8
// speedup vs baseline: 1.3212x; 1.3212x over previous
#include <cuda_runtime.h>
#include <cuda_bf16.h>
#include <cstdint>
#include <math.h>

#define TOKV 21760            // per-view feature tokens: 4*(4096+1024+256+64)
#define AROWS 43520           // 2 views
#define KVSZ  11141120        // 43520*256

__constant__ int c_N[4]   = {4096, 1024, 256, 64};
__constant__ int c_off[4] = {0, 16384, 20480, 21504};
// 8 cross-attn split slots: level, split index, chunk size
__constant__ int c_sl[8] = {0,0,0,0,1,1,2,3};
__constant__ int c_sk[8] = {0,1,2,3,0,1,0,0};
__constant__ int c_ck[8] = {1024,1024,1024,1024,512,512,256,64};
__constant__ int c_S[4]  = {4,2,1,1};
__constant__ int c_s0[4] = {0,4,6,7};

// ---- device scratch (allocations forbidden) ----
__device__ float g_kv[12*KVSZ];                  // K/V for all 6 depths (535 MB)
__device__ __nv_bfloat16 g_ahi[AROWS*256];
__device__ __nv_bfloat16 g_alo[AROWS*256];
__device__ __nv_bfloat16 g_whi[12*256*256];
__device__ __nv_bfloat16 g_wlo[12*256*256];
__device__ float g_bkv[12*256];
__device__ float g_buf[7200000];

struct FeatPtrs { const float* p[8]; };

// ---------------- PTX helpers ----------------
__device__ __forceinline__ uint32_t smem_u32(const void* p){
    uint32_t a;
    asm("{ .reg .u64 t; cvta.to.shared.u64 t, %1; cvt.u32.u64 %0, t; }" : "=r"(a) : "l"(p));
    return a;
}
__device__ __forceinline__ void cp16(uint32_t s, const void* g){
    asm volatile("cp.async.cg.shared.global [%0], [%1], 16;" :: "r"(s), "l"(g) : "memory");
}
__device__ __forceinline__ void cp_commit(){
    asm volatile("cp.async.commit_group;" ::: "memory");
}
template<int N>
__device__ __forceinline__ void cp_wait(){
    asm volatile("cp.async.wait_group %0;" :: "n"(N) : "memory");
}
__device__ __forceinline__ void ldsm4(uint32_t* r, uint32_t a){
    asm volatile("ldmatrix.sync.aligned.m8n8.x4.shared.b16 {%0,%1,%2,%3}, [%4];"
                 : "=r"(r[0]), "=r"(r[1]), "=r"(r[2]), "=r"(r[3]) : "r"(a));
}
__device__ __forceinline__ void mma16816(float* c, const uint32_t* a,
                                         uint32_t b0, uint32_t b1){
    asm volatile(
        "mma.sync.aligned.m16n8k16.row.col.f32.bf16.bf16.f32 "
        "{%0,%1,%2,%3}, {%4,%5,%6,%7}, {%8,%9}, {%0,%1,%2,%3};"
        : "+f"(c[0]), "+f"(c[1]), "+f"(c[2]), "+f"(c[3])
        : "r"(a[0]), "r"(a[1]), "r"(a[2]), "r"(a[3]), "r"(b0), "r"(b1));
}

// ---------------- reductions ----------------
__device__ __forceinline__ float warpSum(float v){
#pragma unroll
    for (int o = 16; o > 0; o >>= 1) v += __shfl_xor_sync(0xffffffffu, v, o);
    return v;
}
__device__ __forceinline__ float warpMax(float v){
#pragma unroll
    for (int o = 16; o > 0; o >>= 1) v = fmaxf(v, __shfl_xor_sync(0xffffffffu, v, o));
    return v;
}
__device__ __forceinline__ float blockSum(float v, float* sh){
    int lane = threadIdx.x & 31, w = threadIdx.x >> 5;
    int nw = blockDim.x >> 5;
    __syncthreads();
    v = warpSum(v);
    if (lane == 0) sh[w] = v;
    __syncthreads();
    if (w == 0){
        float r = (threadIdx.x < nw) ? sh[threadIdx.x] : 0.f;
        r = warpSum(r);
        if (lane == 0) sh[0] = r;
    }
    __syncthreads();
    return sh[0];
}
__device__ __forceinline__ float blockMax(float v, float* sh){
    int lane = threadIdx.x & 31, w = threadIdx.x >> 5;
    int nw = blockDim.x >> 5;
    __syncthreads();
    v = warpMax(v);
    if (lane == 0) sh[w] = v;
    __syncthreads();
    if (w == 0){
        float r = (threadIdx.x < nw) ? sh[threadIdx.x] : -1e30f;
        r = warpMax(r);
        if (lane == 0) sh[0] = r;
    }
    __syncthreads();
    return sh[0];
}

// ---- tokenize + LN normalization -> bf16 hi/lo (coalesced; affine folded into W) ----
__global__ void __launch_bounds__(256) k_tok_ln(FeatPtrs fp,
    __nv_bfloat16* __restrict__ ahi, __nv_bfloat16* __restrict__ alo)
{
    __shared__ float s[256][33];
    __shared__ float ps[8][32], pq[8][32];
    __shared__ float mean[32], rinv[32];
    int r = blockIdx.x, v = blockIdx.y;
    int l = (r < 512) ? 0 : (r < 640) ? 1 : (r < 672) ? 2 : 3;
    int off32 = (l == 0) ? 0 : (l == 1) ? 512 : (l == 2) ? 640 : 672;
    int Nl = c_N[l];
    int idx = r - off32;
    int tpb = Nl >> 5;
    int b = idx / tpb, t0 = (idx % tpb) * 32;
    const float* f = fp.p[v*4 + l];
    int g = threadIdx.x >> 5, t = threadIdx.x & 31;
    for (int cc = g; cc < 256; cc += 8)
        s[cc][t] = f[((size_t)(b*256 + cc))*Nl + t0 + t];
    __syncthreads();
    float sx = 0.f, sq = 0.f;
#pragma unroll
    for (int k = 0; k < 32; k++){
        float x = s[g*32 + k][t];
        sx += x; sq = fmaf(x, x, sq);
    }
    ps[g][t] = sx; pq[g][t] = sq;
    __syncthreads();
    if (threadIdx.x < 32){
        float m = 0.f, qq = 0.f;
#pragma unroll
        for (int gg = 0; gg < 8; gg++){ m += ps[gg][threadIdx.x]; qq += pq[gg][threadIdx.x]; }
        m *= (1.f/256.f);
        float var = qq*(1.f/256.f) - m*m;
        mean[threadIdx.x] = m;
        rinv[threadIdx.x] = rsqrtf(var + 1e-5f);
    }
    __syncthreads();
    int c = threadIdx.x;
    size_t rowbase = (size_t)v*TOKV + c_off[l] + (size_t)b*Nl + t0;
    for (int tt = 0; tt < 32; tt++){
        float val = (s[c][tt] - mean[tt]) * rinv[tt];
        __nv_bfloat16 h = __float2bfloat16(val);
        ahi[(rowbase + tt)*256 + c] = h;
        alo[(rowbase + tt)*256 + c] = __float2bfloat16(val - __bfloat162float(h));
    }
}

// ---- prep weights: Wt[n][k] = g[k]*W[k][n] split bf16 hi/lo; bias'[n] = sum_k b[k]W[k][n]
__global__ void __launch_bounds__(256) k_prep_w(
    const float* __restrict__ wk, const float* __restrict__ wv,
    const float* __restrict__ ng, const float* __restrict__ nb,
    __nv_bfloat16* __restrict__ whi, __nv_bfloat16* __restrict__ wlo,
    float* __restrict__ bkv)
{
    int s = blockIdx.x, n = threadIdx.x;
    int d = s >> 1;
    const float* W = ((s & 1) ? wv : wk) + (size_t)d*65536;
    const float* g = ng + d*256;
    const float* b = nb + d*256;
    float bias = 0.f;
    size_t obase = ((size_t)s*256 + n)*256;
    for (int k = 0; k < 256; k++){
        float w0 = W[k*256 + n];
        bias = fmaf(b[k], w0, bias);
        float w = g[k]*w0;
        __nv_bfloat16 h = __float2bfloat16(w);
        whi[obase + k] = h;
        wlo[obase + k] = __float2bfloat16(w - __bfloat162float(h));
    }
    bkv[s*256 + n] = bias;
}

__global__ void k_init_q(const float* __restrict__ qe, float* __restrict__ q){
    int row = blockIdx.x, c = threadIdx.x;
    q[(size_t)row*256 + c] = qe[(row % 100)*256 + c];
}

// ---- mma.sync KV GEMM: C[slot][43520,256] = A(hi/lo) @ Wt(hi/lo)^T + bias ----
// grid (340 mtiles, 2 n-halves, 12 slots), 256 threads.
// CTA tile 128m x 128n, K chunks of 64, cp.async double buffered.
// SMEM stage layout (64KB): Ah[128][64] @0, Al @16384, Bh[128][64] @32768, Bl @49152.
// XOR swizzle: byteoff = row*128 + ((g ^ (row&7))<<4), g = k-16B-group (0..7).
__global__ void __launch_bounds__(256) k_kvgemm(
    const __nv_bfloat16* __restrict__ Ahi, const __nv_bfloat16* __restrict__ Alo,
    const __nv_bfloat16* __restrict__ Whi, const __nv_bfloat16* __restrict__ Wlo,
    const float* __restrict__ bkv, float* __restrict__ Cbuf)
{
    extern __shared__ char sm[];
    uint32_t sb = smem_u32(sm);
    int tid = threadIdx.x, lane = tid & 31, warp = tid >> 5;
    int mt = blockIdx.x, nh = blockIdx.y, slot = blockIdx.z;
    size_t arow0 = (size_t)mt * 128;
    const __nv_bfloat16* wh = Whi + (size_t)slot*65536 + (size_t)nh*128*256;
    const __nv_bfloat16* wl = Wlo + (size_t)slot*65536 + (size_t)nh*128*256;

    int wm = warp >> 1, wn = warp & 1;           // warp tile: 32m x 64n

    float acc[2][8][4];
#pragma unroll
    for (int mi = 0; mi < 2; mi++)
#pragma unroll
        for (int ni = 0; ni < 8; ni++)
#pragma unroll
            for (int k = 0; k < 4; k++) acc[mi][ni][k] = 0.f;

    // prefetch chunk ck into stage buf
    auto prefetch = [&](int ck, int buf){
        uint32_t stage = sb + buf*65536;
#pragma unroll
        for (int it = 0; it < 4; it++){
            int i = tid + it*256;
            int row = i >> 3, g = i & 7;
            uint32_t so = stage + row*128 + (((g ^ (row & 7)) << 4));
            const __nv_bfloat16* ga = Ahi + (arow0 + row)*256 + ck*64 + g*8;
            const __nv_bfloat16* gal = Alo + (arow0 + row)*256 + ck*64 + g*8;
            cp16(so, ga);
            cp16(so + 16384, gal);
            cp16(so + 32768, wh + row*256 + ck*64 + g*8);
            cp16(so + 49152, wl + row*256 + ck*64 + g*8);
        }
        cp_commit();
    };

    prefetch(0, 0);

    for (int ck = 0; ck < 4; ck++){
        int buf = ck & 1;
        if (ck + 1 < 4){ prefetch(ck + 1, (ck + 1) & 1); cp_wait<1>(); }
        else           { cp_wait<0>(); }
        __syncthreads();

        uint32_t stage = sb + buf*65536;
#pragma unroll
        for (int k16 = 0; k16 < 4; k16++){
            // lane-indexed ldmatrix addresses
            int msel = lane >> 3;                    // matrix 0..3
            int rsub = (msel & 1)*8 + (lane & 7);    // row within 16
            int gg   = k16*2 + (msel >> 1);          // k 16B group
            uint32_t ah[2][4], al[2][4];
#pragma unroll
            for (int mi = 0; mi < 2; mi++){
                int r = wm*32 + mi*16 + rsub;
                uint32_t ad = stage + r*128 + (((gg ^ (r & 7)) << 4));
                ldsm4(ah[mi], ad);
                ldsm4(al[mi], ad + 16384);
            }
            uint32_t bh[4][4], bl[4][4];
#pragma unroll
            for (int nj = 0; nj < 4; nj++){
                int r = wn*64 + nj*16 + rsub;
                uint32_t ad = stage + 32768 + r*128 + (((gg ^ (r & 7)) << 4));
                ldsm4(bh[nj], ad);
                ldsm4(bl[nj], ad + 16384);
            }
#pragma unroll
            for (int mi = 0; mi < 2; mi++)
#pragma unroll
                for (int ni = 0; ni < 8; ni++){
                    int nj = ni >> 1, sel = ni & 1;
                    mma16816(acc[mi][ni], ah[mi], bh[nj][sel], bh[nj][2+sel]);
                    mma16816(acc[mi][ni], ah[mi], bl[nj][sel], bl[nj][2+sel]);
                    mma16816(acc[mi][ni], al[mi], bh[nj][sel], bh[nj][2+sel]);
                }
        }
        __syncthreads();
    }

    // epilogue: add bias, write fp32
    const float* bp = bkv + slot*256;
    float* dst = Cbuf + (size_t)slot*KVSZ;
#pragma unroll
    for (int mi = 0; mi < 2; mi++){
#pragma unroll
        for (int ni = 0; ni < 8; ni++){
            int row = (int)arow0 + wm*32 + mi*16 + (lane >> 2);
            int col = nh*128 + wn*64 + ni*8 + (lane & 3)*2;
            float bx = bp[col], by = bp[col + 1];
            float2 v0 = make_float2(acc[mi][ni][0] + bx, acc[mi][ni][1] + by);
            float2 v1 = make_float2(acc[mi][ni][2] + bx, acc[mi][ni][3] + by);
            *reinterpret_cast<float2*>(dst + (size_t)row*256 + col) = v0;
            *reinterpret_cast<float2*>(dst + (size_t)(row + 8)*256 + col) = v1;
        }
    }
}

// -------- SIMT SGEMM for small Ms: C = op(A)[M,256] @ W[256,N] (+bias) --------
__global__ void __launch_bounds__(256) k_gemm(
    const float* __restrict__ A, const float* __restrict__ W,
    const float* __restrict__ gv, const float* __restrict__ bv,
    const float* __restrict__ bias, float* __restrict__ Cout,
    int M, int N)
{
    __shared__ __align__(16) float As[8][128];
    __shared__ __align__(16) float Bs[8][128];
    int tid = threadIdx.x;
    int m0 = blockIdx.x * 128, n0 = blockIdx.y * 128;
    int arow = tid >> 1, acol = (tid & 1) * 4;
    int brow = tid >> 5, bcol = (tid & 31) * 4;
    int tx = tid & 15, ty = tid >> 4;
    float acc[8][8];
#pragma unroll
    for (int i = 0; i < 8; i++)
#pragma unroll
        for (int j = 0; j < 8; j++) acc[i][j] = 0.f;

    const bool pre = (gv != nullptr);
    for (int k0 = 0; k0 < 256; k0 += 8){
        float4 av = make_float4(0.f,0.f,0.f,0.f);
        int gm = m0 + arow;
        if (gm < M) av = *reinterpret_cast<const float4*>(A + (size_t)gm*256 + k0 + acol);
        if (pre){
            float4 gg = *reinterpret_cast<const float4*>(gv + k0 + acol);
            float4 bb = *reinterpret_cast<const float4*>(bv + k0 + acol);
            av.x = fmaf(av.x, gg.x, bb.x); av.y = fmaf(av.y, gg.y, bb.y);
            av.z = fmaf(av.z, gg.z, bb.z); av.w = fmaf(av.w, gg.w, bb.w);
        }
        As[acol+0][arow] = av.x; As[acol+1][arow] = av.y;
        As[acol+2][arow] = av.z; As[acol+3][arow] = av.w;
        *reinterpret_cast<float4*>(&Bs[brow][bcol]) =
            *reinterpret_cast<const float4*>(W + (size_t)(k0 + brow)*N + n0 + bcol);
        __syncthreads();
#pragma unroll
        for (int kk = 0; kk < 8; kk++){
            float a[8], b[8];
            *reinterpret_cast<float4*>(a)     = *reinterpret_cast<float4*>(&As[kk][ty*8]);
            *reinterpret_cast<float4*>(a + 4) = *reinterpret_cast<float4*>(&As[kk][ty*8 + 4]);
            *reinterpret_cast<float4*>(b)     = *reinterpret_cast<float4*>(&Bs[kk][tx*8]);
            *reinterpret_cast<float4*>(b + 4) = *reinterpret_cast<float4*>(&Bs[kk][tx*8 + 4]);
#pragma unroll
            for (int i = 0; i < 8; i++)
#pragma unroll
                for (int j = 0; j < 8; j++) acc[i][j] = fmaf(a[i], b[j], acc[i][j]);
        }
        __syncthreads();
    }
#pragma unroll
    for (int i = 0; i < 8; i++){
        int gm = m0 + ty*8 + i;
        if (gm < M){
#pragma unroll
            for (int j = 0; j < 8; j += 4){
                int gn = n0 + tx*8 + j;
                float4 o;
                o.x = acc[i][j+0]; o.y = acc[i][j+1]; o.z = acc[i][j+2]; o.w = acc[i][j+3];
                if (bias){
                    o.x += bias[gn+0]; o.y += bias[gn+1];
                    o.z += bias[gn+2]; o.w += bias[gn+3];
                }
                *reinterpret_cast<float4*>(Cout + (size_t)gm*N + gn) = o;
            }
        }
    }
}

// ---------------- self-attention over 100 keys, per (h, b, l) ----------------
__global__ void __launch_bounds__(128) k_sa(const float* __restrict__ qkv,
                                            float* __restrict__ osa){
    __shared__ float sK[100][32];
    __shared__ float sV[100][32];
    int h = blockIdx.x, b = blockIdx.y, l = blockIdx.z;
    int lb = l*4 + b;
    const float* qb = qkv + (size_t)lb*100*768;
    for (int idx = threadIdx.x; idx < 3200; idx += 128){
        int j = idx >> 5, c = idx & 31;
        sK[j][c] = qb[(size_t)j*768 + 256 + h*32 + c];
        sV[j][c] = qb[(size_t)j*768 + 512 + h*32 + c];
    }
    __syncthreads();
    int i = threadIdx.x;
    if (i < 100){
        float Q[32];
#pragma unroll
        for (int c = 0; c < 32; c++) Q[c] = qb[(size_t)i*768 + h*32 + c];
        float m = -1e30f, s = 0.f, acc[32];
#pragma unroll
        for (int c = 0; c < 32; c++) acc[c] = 0.f;
        for (int j = 0; j < 100; j++){
            float d = 0.f;
#pragma unroll
            for (int c = 0; c < 32; c++) d = fmaf(Q[c], sK[j][c], d);
            d *= 0.17677669529663687f;
            if (d > m){
                float f = __expf(m - d);
                m = d; s = fmaf(s, f, 1.f);
#pragma unroll
                for (int c = 0; c < 32; c++) acc[c] = fmaf(acc[c], f, sV[j][c]);
            } else {
                float p = __expf(d - m);
                s += p;
#pragma unroll
                for (int c = 0; c < 32; c++) acc[c] = fmaf(p, sV[j][c], acc[c]);
            }
        }
        float inv = 1.f / s;
        float* o = osa + (size_t)(lb*100 + i)*256 + h*32;
#pragma unroll
        for (int c = 0; c < 32; c++) o[c] = acc[c]*inv;
    }
}

// ---------------- row LN (normalization only) ----------------
__global__ void __launch_bounds__(256) k_ln_rows(const float* __restrict__ in,
                                                 float* __restrict__ out){
    __shared__ float sh[32];
    int row = blockIdx.x, c = threadIdx.x;
    float x = in[(size_t)row*256 + c];
    float m = blockSum(x, sh) * (1.f/256.f);
    float d = x - m;
    float var = blockSum(d*d, sh) * (1.f/256.f);
    out[(size_t)row*256 + c] = d * rsqrtf(var + 1e-5f);
}

// ---------------- cross-attention flash partials ----------------
__global__ void __launch_bounds__(128) k_cross(
    const float* __restrict__ qn, const float* __restrict__ Kg,
    const float* __restrict__ Vg, float* __restrict__ pm,
    float* __restrict__ ps, float* __restrict__ pacc)
{
    __shared__ float sK[64][32];
    __shared__ float sV[64][32];
    int ss = blockIdx.x, h = blockIdx.y, vb = blockIdx.z;
    int v = vb >> 2, b = vb & 3;
    int l = c_sl[ss];
    int Nl = c_N[l];
    int ck = c_ck[ss];
    int kbeg = c_sk[ss]*ck;
    int lb = l*4 + b;
    size_t kvbase = ((size_t)v*TOKV + c_off[l] + (size_t)b*Nl)*256 + h*32;
    const float* Kp = Kg + kvbase;
    const float* Vp = Vg + kvbase;
    int i = threadIdx.x;
    float Q[32];
    if (i < 100){
        const float* qp = qn + (size_t)(lb*100 + i)*256 + h*32;
#pragma unroll
        for (int c = 0; c < 32; c++) Q[c] = qp[c];
    }
    float m = -1e30f, s = 0.f, acc[32];
#pragma unroll
    for (int c = 0; c < 32; c++) acc[c] = 0.f;
    for (int kc = kbeg; kc < kbeg + ck; kc += 64){
        __syncthreads();
        for (int idx = threadIdx.x; idx < 2048; idx += 128){
            int j = idx >> 5, c = idx & 31;
            sK[j][c] = Kp[(size_t)(kc + j)*256 + c];
            sV[j][c] = Vp[(size_t)(kc + j)*256 + c];
        }
        __syncthreads();
        if (i < 100){
            for (int j = 0; j < 64; j++){
                float d = 0.f;
#pragma unroll
                for (int c = 0; c < 32; c++) d = fmaf(Q[c], sK[j][c], d);
                d *= 0.17677669529663687f;
                if (d > m){
                    float f = __expf(m - d);
                    m = d; s = fmaf(s, f, 1.f);
#pragma unroll
                    for (int c = 0; c < 32; c++) acc[c] = fmaf(acc[c], f, sV[j][c]);
                } else {
                    float p = __expf(d - m);
                    s += p;
#pragma unroll
                    for (int c = 0; c < 32; c++) acc[c] = fmaf(p, sV[j][c], acc[c]);
                }
            }
        }
    }
    if (i < 100){
        int slot = (vb*8 + h)*8 + ss;
        pm[slot*100 + i] = m;
        ps[slot*100 + i] = s;
        float* pa = pacc + (size_t)(slot*100 + i)*32;
#pragma unroll
        for (int c = 0; c < 32; c++) pa[c] = acc[c];
    }
}

__global__ void __launch_bounds__(128) k_combine(
    const float* __restrict__ pm, const float* __restrict__ ps,
    const float* __restrict__ pacc, float* __restrict__ ocr)
{
    int l = blockIdx.x, h = blockIdx.y, vb = blockIdx.z;
    int i = threadIdx.x;
    if (i >= 100) return;
    int S = c_S[l], s0 = c_s0[l];
    int base = (vb*8 + h)*8 + s0;
    float M = -1e30f;
    for (int k = 0; k < S; k++) M = fmaxf(M, pm[(base + k)*100 + i]);
    float Ss = 0.f, acc[32];
#pragma unroll
    for (int c = 0; c < 32; c++) acc[c] = 0.f;
    for (int k = 0; k < S; k++){
        int slot = base + k;
        float f = __expf(pm[slot*100 + i] - M);
        Ss = fmaf(ps[slot*100 + i], f, Ss);
        const float* pa = pacc + (size_t)(slot*100 + i)*32;
#pragma unroll
        for (int c = 0; c < 32; c++) acc[c] = fmaf(pa[c], f, acc[c]);
    }
    float inv = 1.f / Ss;
    int v = vb >> 2, b = vb & 3;
    int lb = l*4 + b;
    float* o = ocr + (size_t)v*409600 + (size_t)(lb*100 + i)*256 + h*32;
#pragma unroll
    for (int c = 0; c < 32; c++) o[c] = acc[c]*inv;
}

// ---------------- matching score ms = q1 @ q2^T per lb ----------------
__global__ void __launch_bounds__(256) k_match(const float* __restrict__ q12,
                                               float* __restrict__ ms){
    __shared__ float sA[100][33];
    __shared__ float sB[100][33];
    int lb = blockIdx.x;
    int tx = threadIdx.x & 15, ty = threadIdx.x >> 4;
    const float* q1 = q12 + (size_t)lb*25600;
    const float* q2 = q12 + 409600 + (size_t)lb*25600;
    float acc[7][7];
#pragma unroll
    for (int a = 0; a < 7; a++)
#pragma unroll
        for (int bq = 0; bq < 7; bq++) acc[a][bq] = 0.f;
    for (int k0 = 0; k0 < 256; k0 += 32){
        __syncthreads();
        for (int idx = threadIdx.x; idx < 3200; idx += 256){
            int r = idx >> 5, kk = idx & 31;
            sA[r][kk] = q1[(size_t)r*256 + k0 + kk];
            sB[r][kk] = q2[(size_t)r*256 + k0 + kk];
        }
        __syncthreads();
        for (int kk = 0; kk < 32; kk++){
            float a[7], b[7];
#pragma unroll
            for (int ii = 0; ii < 7; ii++){
                int i = ty + 16*ii;
                a[ii] = (i < 100) ? sA[i][kk] : 0.f;
            }
#pragma unroll
            for (int jj = 0; jj < 7; jj++){
                int j = tx + 16*jj;
                b[jj] = (j < 100) ? sB[j][kk] : 0.f;
            }
#pragma unroll
            for (int ii = 0; ii < 7; ii++)
#pragma unroll
                for (int jj = 0; jj < 7; jj++) acc[ii][jj] = fmaf(a[ii], b[jj], acc[ii][jj]);
        }
    }
#pragma unroll
    for (int ii = 0; ii < 7; ii++){
        int i = ty + 16*ii;
        if (i < 100){
#pragma unroll
            for (int jj = 0; jj < 7; jj++){
                int j = tx + 16*jj;
                if (j < 100) ms[(size_t)lb*10000 + i*100 + j] = acc[ii][jj];
            }
        }
    }
}

// ---------------- row (mode 0) / column (mode 1) softmax of ms ----------------
__global__ void __launch_bounds__(128) k_softmax_ms(const float* __restrict__ ms,
                                                    float* __restrict__ wr,
                                                    float* __restrict__ wc){
    __shared__ float sh[32];
    int x = blockIdx.x, lb = blockIdx.y, mode = blockIdx.z;
    int t = threadIdx.x;
    const float* base = ms + (size_t)lb*10000;
    int idx = (mode == 0) ? (x*100 + t) : (t*100 + x);
    float v = (t < 100) ? base[idx] : -1e30f;
    float M = blockMax(v, sh);
    float p = (t < 100) ? __expf(v - M) : 0.f;
    float S = blockSum(p, sh);
    if (t < 100){
        float w = p / S;
        if (mode == 0) wr[(size_t)lb*10000 + x*100 + t] = w;
        else           wc[(size_t)lb*10000 + t*100 + x] = w;
    }
}

// -------- fuse (4 queries/block): t = qsa+q1+q2+Wr@q2+Wc^T@q1; softmax over c ----
__global__ void __launch_bounds__(256) k_fuse(
    const float* __restrict__ qsa, const float* __restrict__ q12,
    const float* __restrict__ wr, const float* __restrict__ wc,
    float* __restrict__ outp)
{
    __shared__ float swr[4][100];
    __shared__ float swc[4][100];
    __shared__ float sh[32];
    int i0 = blockIdx.x * 4, lb = blockIdx.y, c = threadIdx.x;
    const float* q1 = q12 + (size_t)lb*25600;
    const float* q2 = q12 + 409600 + (size_t)lb*25600;
    for (int idx = c; idx < 400; idx += 256){
        int ii = idx / 100, j = idx % 100;
        swr[ii][j] = wr[(size_t)lb*10000 + (i0+ii)*100 + j];
        swc[ii][j] = wc[(size_t)lb*10000 + j*100 + (i0+ii)];
    }
    __syncthreads();
    float acc[4];
#pragma unroll
    for (int ii = 0; ii < 4; ii++)
        acc[ii] = qsa[(size_t)(lb*100 + i0+ii)*256 + c]
                + q1[(size_t)(i0+ii)*256 + c] + q2[(size_t)(i0+ii)*256 + c];
    for (int j = 0; j < 100; j++){
        float q1v = q1[(size_t)j*256 + c];
        float q2v = q2[(size_t)j*256 + c];
#pragma unroll
        for (int ii = 0; ii < 4; ii++){
            acc[ii] = fmaf(swr[ii][j], q2v, acc[ii]);
            acc[ii] = fmaf(swc[ii][j], q1v, acc[ii]);
        }
    }
#pragma unroll
    for (int ii = 0; ii < 4; ii++){
        float M = blockMax(acc[ii], sh);
        float e = __expf(acc[ii] - M);
        float S = blockSum(e, sh);
        outp[(size_t)(lb*100 + i0+ii)*256 + c] = e / S;
    }
}

// ---------------- host ----------------
extern "C" void kernel_launch(void* const* d_in, const int* in_sizes, int n_in,
                              void* d_out, int out_size)
{
    float* arena;   cudaGetSymbolAddress((void**)&arena, g_buf);
    float* kvbuf;   cudaGetSymbolAddress((void**)&kvbuf, g_kv);
    __nv_bfloat16 *ahi, *alo, *whi, *wlo;
    cudaGetSymbolAddress((void**)&ahi, g_ahi);
    cudaGetSymbolAddress((void**)&alo, g_alo);
    cudaGetSymbolAddress((void**)&whi, g_whi);
    cudaGetSymbolAddress((void**)&wlo, g_wlo);
    float* bkv;     cudaGetSymbolAddress((void**)&bkv, g_bkv);

    float* q    = arena;
    float* qkv  = arena + 409600;
    float* osa  = arena + 1638400;
    float* qsa  = arena + 2048000;
    float* qln  = arena + 2457600;
    float* qn   = arena + 2867200;
    float* ocr  = arena + 3276800;
    float* q12  = arena + 4096000;
    float* ms   = arena + 4915200;
    float* wr   = arena + 5075200;
    float* wc   = arena + 5235200;
    float* pm   = arena + 5395200;
    float* ps   = arena + 5446400;
    float* pacc = arena + 5497600;

    FeatPtrs fp;
    for (int i = 0; i < 8; i++) fp.p[i] = (const float*)d_in[i];
    const float* qe   = (const float*)d_in[8];
    const float* ng   = (const float*)d_in[9];
    const float* nb   = (const float*)d_in[10];
    const float* wq   = (const float*)d_in[11];
    const float* wk   = (const float*)d_in[12];
    const float* wv   = (const float*)d_in[13];
    const float* wp   = (const float*)d_in[14];
    const float* bp   = (const float*)d_in[15];
    const float* wqkv = (const float*)d_in[16];
    const float* swp  = (const float*)d_in[17];
    const float* sbp  = (const float*)d_in[18];

    cudaFuncSetAttribute(k_kvgemm, cudaFuncAttributeMaxDynamicSharedMemorySize, 131072);

    k_tok_ln<<<dim3(680, 2), 256>>>(fp, ahi, alo);
    k_prep_w<<<12, 256>>>(wk, wv, ng, nb, whi, wlo, bkv);
    k_init_q<<<1600, 256>>>(qe, q);
    k_kvgemm<<<dim3(340, 2, 12), 256, 131072>>>(ahi, alo, whi, wlo, bkv, kvbuf);

    for (int d = 0; d < 6; d++){
        const float* g = ng + d*256;
        const float* b = nb + d*256;
        k_gemm<<<dim3(13, 6), 256>>>(q, wqkv + (size_t)d*256*768,
                                     nullptr, nullptr, nullptr, qkv, 1600, 768);
        k_sa<<<dim3(8, 4, 4), 128>>>(qkv, osa);
        k_gemm<<<dim3(13, 2), 256>>>(osa, swp + (size_t)d*65536,
                                     nullptr, nullptr, sbp + d*256, qsa, 1600, 256);
        k_ln_rows<<<1600, 256>>>(qsa, qln);
        k_gemm<<<dim3(13, 2), 256>>>(qln, wq + (size_t)d*65536,
                                     g, b, nullptr, qn, 1600, 256);
        k_cross<<<dim3(8, 8, 8), 128>>>(qn, kvbuf + (size_t)(2*d)*KVSZ,
                                        kvbuf + (size_t)(2*d+1)*KVSZ, pm, ps, pacc);
        k_combine<<<dim3(4, 8, 8), 128>>>(pm, ps, pacc, ocr);
        k_gemm<<<dim3(25, 2), 256>>>(ocr, wp + (size_t)d*65536,
                                     nullptr, nullptr, bp + d*256, q12, 3200, 256);
        k_match<<<16, 256>>>(q12, ms);
        k_softmax_ms<<<dim3(100, 16, 2), 128>>>(ms, wr, wc);
        k_fuse<<<dim3(25, 16), 256>>>(qsa, q12, wr, wc,
                                      (d == 5) ? (float*)d_out : q);
    }
}

// round 9
// speedup vs baseline: 1.3753x; 1.0409x over previous
#include <cuda_runtime.h>
#include <cuda_bf16.h>
#include <cstdint>
#include <math.h>

#define TOKV 21760            // per-view feature tokens: 4*(4096+1024+256+64)
#define AROWS 43520           // 2 views
#define KVSZ  11141120        // 43520*256

__constant__ int c_N[4]   = {4096, 1024, 256, 64};
__constant__ int c_off[4] = {0, 16384, 20480, 21504};
// 8 cross-attn split slots: level, split index, chunk size
__constant__ int c_sl[8] = {0,0,0,0,1,1,2,3};
__constant__ int c_sk[8] = {0,1,2,3,0,1,0,0};
__constant__ int c_ck[8] = {1024,1024,1024,1024,512,512,256,64};
__constant__ int c_S[4]  = {4,2,1,1};
__constant__ int c_s0[4] = {0,4,6,7};

// ---- device scratch (allocations forbidden) ----
__device__ float g_kv[12*KVSZ];                  // K/V for all 6 depths (535 MB)
__device__ __nv_bfloat16 g_ahi[AROWS*256];
__device__ __nv_bfloat16 g_alo[AROWS*256];
__device__ __nv_bfloat16 g_whi[12*256*256];
__device__ __nv_bfloat16 g_wlo[12*256*256];
__device__ float g_bkv[12*256];
__device__ float g_buf[7200000];

struct FeatPtrs { const float* p[8]; };

// ---------------- PTX helpers ----------------
__device__ __forceinline__ uint32_t smem_u32(const void* p){
    uint32_t a;
    asm("{ .reg .u64 t; cvta.to.shared.u64 t, %1; cvt.u32.u64 %0, t; }" : "=r"(a) : "l"(p));
    return a;
}
__device__ __forceinline__ void cp16(uint32_t s, const void* g){
    asm volatile("cp.async.cg.shared.global [%0], [%1], 16;" :: "r"(s), "l"(g) : "memory");
}
__device__ __forceinline__ void cp_commit(){
    asm volatile("cp.async.commit_group;" ::: "memory");
}
template<int N>
__device__ __forceinline__ void cp_wait(){
    asm volatile("cp.async.wait_group %0;" :: "n"(N) : "memory");
}
__device__ __forceinline__ void ldsm4(uint32_t* r, uint32_t a){
    asm volatile("ldmatrix.sync.aligned.m8n8.x4.shared.b16 {%0,%1,%2,%3}, [%4];"
                 : "=r"(r[0]), "=r"(r[1]), "=r"(r[2]), "=r"(r[3]) : "r"(a));
}
__device__ __forceinline__ void mma16816(float* c, const uint32_t* a,
                                         uint32_t b0, uint32_t b1){
    asm volatile(
        "mma.sync.aligned.m16n8k16.row.col.f32.bf16.bf16.f32 "
        "{%0,%1,%2,%3}, {%4,%5,%6,%7}, {%8,%9}, {%0,%1,%2,%3};"
        : "+f"(c[0]), "+f"(c[1]), "+f"(c[2]), "+f"(c[3])
        : "r"(a[0]), "r"(a[1]), "r"(a[2]), "r"(a[3]), "r"(b0), "r"(b1));
}

// ---------------- reductions ----------------
__device__ __forceinline__ float warpSum(float v){
#pragma unroll
    for (int o = 16; o > 0; o >>= 1) v += __shfl_xor_sync(0xffffffffu, v, o);
    return v;
}
__device__ __forceinline__ float warpMax(float v){
#pragma unroll
    for (int o = 16; o > 0; o >>= 1) v = fmaxf(v, __shfl_xor_sync(0xffffffffu, v, o));
    return v;
}
__device__ __forceinline__ float blockSum(float v, float* sh){
    int lane = threadIdx.x & 31, w = threadIdx.x >> 5;
    int nw = blockDim.x >> 5;
    __syncthreads();
    v = warpSum(v);
    if (lane == 0) sh[w] = v;
    __syncthreads();
    if (w == 0){
        float r = (threadIdx.x < nw) ? sh[threadIdx.x] : 0.f;
        r = warpSum(r);
        if (lane == 0) sh[0] = r;
    }
    __syncthreads();
    return sh[0];
}
__device__ __forceinline__ float blockMax(float v, float* sh){
    int lane = threadIdx.x & 31, w = threadIdx.x >> 5;
    int nw = blockDim.x >> 5;
    __syncthreads();
    v = warpMax(v);
    if (lane == 0) sh[w] = v;
    __syncthreads();
    if (w == 0){
        float r = (threadIdx.x < nw) ? sh[threadIdx.x] : -1e30f;
        r = warpMax(r);
        if (lane == 0) sh[0] = r;
    }
    __syncthreads();
    return sh[0];
}

// ---- tokenize + LN normalization -> bf16 hi/lo (coalesced; affine folded into W) ----
__global__ void __launch_bounds__(256) k_tok_ln(FeatPtrs fp,
    __nv_bfloat16* __restrict__ ahi, __nv_bfloat16* __restrict__ alo)
{
    __shared__ float s[256][33];
    __shared__ float ps[8][32], pq[8][32];
    __shared__ float mean[32], rinv[32];
    int r = blockIdx.x, v = blockIdx.y;
    int l = (r < 512) ? 0 : (r < 640) ? 1 : (r < 672) ? 2 : 3;
    int off32 = (l == 0) ? 0 : (l == 1) ? 512 : (l == 2) ? 640 : 672;
    int Nl = c_N[l];
    int idx = r - off32;
    int tpb = Nl >> 5;
    int b = idx / tpb, t0 = (idx % tpb) * 32;
    const float* f = fp.p[v*4 + l];
    int g = threadIdx.x >> 5, t = threadIdx.x & 31;
    for (int cc = g; cc < 256; cc += 8)
        s[cc][t] = f[((size_t)(b*256 + cc))*Nl + t0 + t];
    __syncthreads();
    float sx = 0.f, sq = 0.f;
#pragma unroll
    for (int k = 0; k < 32; k++){
        float x = s[g*32 + k][t];
        sx += x; sq = fmaf(x, x, sq);
    }
    ps[g][t] = sx; pq[g][t] = sq;
    __syncthreads();
    if (threadIdx.x < 32){
        float m = 0.f, qq = 0.f;
#pragma unroll
        for (int gg = 0; gg < 8; gg++){ m += ps[gg][threadIdx.x]; qq += pq[gg][threadIdx.x]; }
        m *= (1.f/256.f);
        float var = qq*(1.f/256.f) - m*m;
        mean[threadIdx.x] = m;
        rinv[threadIdx.x] = rsqrtf(var + 1e-5f);
    }
    __syncthreads();
    int c = threadIdx.x;
    size_t rowbase = (size_t)v*TOKV + c_off[l] + (size_t)b*Nl + t0;
    for (int tt = 0; tt < 32; tt++){
        float val = (s[c][tt] - mean[tt]) * rinv[tt];
        __nv_bfloat16 h = __float2bfloat16(val);
        ahi[(rowbase + tt)*256 + c] = h;
        alo[(rowbase + tt)*256 + c] = __float2bfloat16(val - __bfloat162float(h));
    }
}

// ---- prep KV weights: Wt[n][k] = g[k]*W[k][n] bf16 hi/lo; bias'[n] = b@W ----
__global__ void __launch_bounds__(256) k_prep_w(
    const float* __restrict__ wk, const float* __restrict__ wv,
    const float* __restrict__ ng, const float* __restrict__ nb,
    __nv_bfloat16* __restrict__ whi, __nv_bfloat16* __restrict__ wlo,
    float* __restrict__ bkv)
{
    int s = blockIdx.x, n = threadIdx.x;
    int d = s >> 1;
    const float* W = ((s & 1) ? wv : wk) + (size_t)d*65536;
    const float* g = ng + d*256;
    const float* b = nb + d*256;
    float bias = 0.f;
    size_t obase = ((size_t)s*256 + n)*256;
    for (int k = 0; k < 256; k++){
        float w0 = W[k*256 + n];
        bias = fmaf(b[k], w0, bias);
        float w = g[k]*w0;
        __nv_bfloat16 h = __float2bfloat16(w);
        whi[obase + k] = h;
        wlo[obase + k] = __float2bfloat16(w - __bfloat162float(h));
    }
    bkv[s*256 + n] = bias;
}

// ---- prep Q weights (fp32): wqf[k][n] = g[k]*wq[k][n]; bqf[n] = b@wq ----
__global__ void __launch_bounds__(256) k_prep_wq(
    const float* __restrict__ wq, const float* __restrict__ ng,
    const float* __restrict__ nb, float* __restrict__ wqf,
    float* __restrict__ bqf)
{
    int d = blockIdx.x, n = threadIdx.x;
    const float* W = wq + (size_t)d*65536;
    const float* g = ng + d*256;
    const float* b = nb + d*256;
    float bias = 0.f;
    for (int k = 0; k < 256; k++){
        float w0 = W[k*256 + n];
        bias = fmaf(b[k], w0, bias);
        wqf[(size_t)d*65536 + k*256 + n] = g[k]*w0;
    }
    bqf[d*256 + n] = bias;
}

__global__ void k_init_q(const float* __restrict__ qe, float* __restrict__ q){
    int row = blockIdx.x, c = threadIdx.x;
    q[(size_t)row*256 + c] = qe[(row % 100)*256 + c];
}

// ---- mma.sync KV GEMM: C[slot][43520,256] = A(hi/lo) @ Wt(hi/lo)^T + bias ----
__global__ void __launch_bounds__(256) k_kvgemm(
    const __nv_bfloat16* __restrict__ Ahi, const __nv_bfloat16* __restrict__ Alo,
    const __nv_bfloat16* __restrict__ Whi, const __nv_bfloat16* __restrict__ Wlo,
    const float* __restrict__ bkv, float* __restrict__ Cbuf)
{
    extern __shared__ char sm[];
    uint32_t sb = smem_u32(sm);
    int tid = threadIdx.x, lane = tid & 31, warp = tid >> 5;
    int mt = blockIdx.x, nh = blockIdx.y, slot = blockIdx.z;
    size_t arow0 = (size_t)mt * 128;
    const __nv_bfloat16* wh = Whi + (size_t)slot*65536 + (size_t)nh*128*256;
    const __nv_bfloat16* wl = Wlo + (size_t)slot*65536 + (size_t)nh*128*256;

    int wm = warp >> 1, wn = warp & 1;           // warp tile: 32m x 64n

    float acc[2][8][4];
#pragma unroll
    for (int mi = 0; mi < 2; mi++)
#pragma unroll
        for (int ni = 0; ni < 8; ni++)
#pragma unroll
            for (int k = 0; k < 4; k++) acc[mi][ni][k] = 0.f;

    auto prefetch = [&](int ck, int buf){
        uint32_t stage = sb + buf*65536;
#pragma unroll
        for (int it = 0; it < 4; it++){
            int i = tid + it*256;
            int row = i >> 3, g = i & 7;
            uint32_t so = stage + row*128 + (((g ^ (row & 7)) << 4));
            cp16(so,         Ahi + (arow0 + row)*256 + ck*64 + g*8);
            cp16(so + 16384, Alo + (arow0 + row)*256 + ck*64 + g*8);
            cp16(so + 32768, wh + row*256 + ck*64 + g*8);
            cp16(so + 49152, wl + row*256 + ck*64 + g*8);
        }
        cp_commit();
    };

    prefetch(0, 0);

    for (int ck = 0; ck < 4; ck++){
        int buf = ck & 1;
        if (ck + 1 < 4){ prefetch(ck + 1, (ck + 1) & 1); cp_wait<1>(); }
        else           { cp_wait<0>(); }
        __syncthreads();

        uint32_t stage = sb + buf*65536;
#pragma unroll
        for (int k16 = 0; k16 < 4; k16++){
            int msel = lane >> 3;
            int rsub = (msel & 1)*8 + (lane & 7);
            int gg   = k16*2 + (msel >> 1);
            uint32_t ah[2][4], al[2][4];
#pragma unroll
            for (int mi = 0; mi < 2; mi++){
                int r = wm*32 + mi*16 + rsub;
                uint32_t ad = stage + r*128 + (((gg ^ (r & 7)) << 4));
                ldsm4(ah[mi], ad);
                ldsm4(al[mi], ad + 16384);
            }
            uint32_t bh[4][4], bl[4][4];
#pragma unroll
            for (int nj = 0; nj < 4; nj++){
                int r = wn*64 + nj*16 + rsub;
                uint32_t ad = stage + 32768 + r*128 + (((gg ^ (r & 7)) << 4));
                ldsm4(bh[nj], ad);
                ldsm4(bl[nj], ad + 16384);
            }
#pragma unroll
            for (int mi = 0; mi < 2; mi++)
#pragma unroll
                for (int ni = 0; ni < 8; ni++){
                    int nj = ni >> 1, sel = ni & 1;
                    mma16816(acc[mi][ni], ah[mi], bh[nj][sel], bh[nj][2+sel]);
                    mma16816(acc[mi][ni], ah[mi], bl[nj][sel], bl[nj][2+sel]);
                    mma16816(acc[mi][ni], al[mi], bh[nj][sel], bh[nj][2+sel]);
                }
        }
        __syncthreads();
    }

    // epilogue: stage fp32 tile in smem (stride 132), stream out coalesced
    float* st = reinterpret_cast<float*>(sm);
#pragma unroll
    for (int mi = 0; mi < 2; mi++)
#pragma unroll
        for (int ni = 0; ni < 8; ni++){
            int r0 = wm*32 + mi*16 + (lane >> 2);
            int c0 = wn*64 + ni*8 + (lane & 3)*2;
            *reinterpret_cast<float2*>(st + r0*132 + c0)       = make_float2(acc[mi][ni][0], acc[mi][ni][1]);
            *reinterpret_cast<float2*>(st + (r0 + 8)*132 + c0) = make_float2(acc[mi][ni][2], acc[mi][ni][3]);
        }
    __syncthreads();
    const float4* bp4 = reinterpret_cast<const float4*>(bkv + slot*256 + nh*128);
    float* dst = Cbuf + (size_t)slot*KVSZ + arow0*256 + nh*128;
#pragma unroll
    for (int it = 0; it < 16; it++){
        int i = tid + it*256;
        int row = i >> 5, q = i & 31;
        float4 v = *reinterpret_cast<float4*>(st + row*132 + q*4);
        float4 bb = bp4[q];
        v.x += bb.x; v.y += bb.y; v.z += bb.z; v.w += bb.w;
        *reinterpret_cast<float4*>(dst + (size_t)row*256 + q*4) = v;
    }
}

// -------- SIMT SGEMM 64x128 tile: C = op(A)[M,256] @ W[256,N] (+bias) --------
// ln != 0: normalize A rows (mean/var over k) on load. Grids must tile M by 64 exactly.
__global__ void __launch_bounds__(256) k_gemm64(
    const float* __restrict__ A, const float* __restrict__ W,
    const float* __restrict__ bias, float* __restrict__ Cout,
    int M, int N, int ln)
{
    __shared__ __align__(16) float As[8][64];
    __shared__ __align__(16) float Bs[8][128];
    __shared__ float2 red[64][4];
    __shared__ float s_mean[64], s_rinv[64];
    int tid = threadIdx.x;
    int m0 = blockIdx.x * 64, n0 = blockIdx.y * 128;

    if (ln){
        int r = tid >> 2, qq = tid & 3;
        const float4* ap = reinterpret_cast<const float4*>(A + (size_t)(m0 + r)*256 + qq*64);
        float sx = 0.f, sq = 0.f;
#pragma unroll
        for (int k = 0; k < 16; k++){
            float4 x = ap[k];
            sx += x.x + x.y + x.z + x.w;
            sq = fmaf(x.x, x.x, sq); sq = fmaf(x.y, x.y, sq);
            sq = fmaf(x.z, x.z, sq); sq = fmaf(x.w, x.w, sq);
        }
        red[r][qq] = make_float2(sx, sq);
        __syncthreads();
        if (tid < 64){
            float m = 0.f, q2 = 0.f;
#pragma unroll
            for (int j = 0; j < 4; j++){ m += red[tid][j].x; q2 += red[tid][j].y; }
            m *= (1.f/256.f);
            float var = q2*(1.f/256.f) - m*m;
            s_mean[tid] = m;
            s_rinv[tid] = rsqrtf(var + 1e-5f);
        }
        __syncthreads();
    }

    int tx = tid & 15, ty = tid >> 4;
    float acc[4][8];
#pragma unroll
    for (int i = 0; i < 4; i++)
#pragma unroll
        for (int j = 0; j < 8; j++) acc[i][j] = 0.f;

    int arow = tid >> 1, acol = (tid & 1)*4;
    int brow = tid >> 5, bcol = (tid & 31)*4;

    for (int k0 = 0; k0 < 256; k0 += 8){
        if (tid < 128){
            float4 av = *reinterpret_cast<const float4*>(A + (size_t)(m0 + arow)*256 + k0 + acol);
            if (ln){
                float m = s_mean[arow], ri = s_rinv[arow];
                av.x = (av.x - m)*ri; av.y = (av.y - m)*ri;
                av.z = (av.z - m)*ri; av.w = (av.w - m)*ri;
            }
            As[acol+0][arow] = av.x; As[acol+1][arow] = av.y;
            As[acol+2][arow] = av.z; As[acol+3][arow] = av.w;
        }
        *reinterpret_cast<float4*>(&Bs[brow][bcol]) =
            *reinterpret_cast<const float4*>(W + (size_t)(k0 + brow)*N + n0 + bcol);
        __syncthreads();
#pragma unroll
        for (int kk = 0; kk < 8; kk++){
            float a[4], b[8];
            *reinterpret_cast<float4*>(a)     = *reinterpret_cast<float4*>(&As[kk][ty*4]);
            *reinterpret_cast<float4*>(b)     = *reinterpret_cast<float4*>(&Bs[kk][tx*8]);
            *reinterpret_cast<float4*>(b + 4) = *reinterpret_cast<float4*>(&Bs[kk][tx*8 + 4]);
#pragma unroll
            for (int i = 0; i < 4; i++)
#pragma unroll
                for (int j = 0; j < 8; j++) acc[i][j] = fmaf(a[i], b[j], acc[i][j]);
        }
        __syncthreads();
    }
#pragma unroll
    for (int i = 0; i < 4; i++){
        int gm = m0 + ty*4 + i;
#pragma unroll
        for (int j = 0; j < 8; j += 4){
            int gn = n0 + tx*8 + j;
            float4 o;
            o.x = acc[i][j+0]; o.y = acc[i][j+1]; o.z = acc[i][j+2]; o.w = acc[i][j+3];
            if (bias){
                o.x += bias[gn+0]; o.y += bias[gn+1];
                o.z += bias[gn+2]; o.w += bias[gn+3];
            }
            *reinterpret_cast<float4*>(Cout + (size_t)gm*N + gn) = o;
        }
    }
}

// ---------------- self-attention over 100 keys, per (h, b, l) ----------------
__global__ void __launch_bounds__(128) k_sa(const float* __restrict__ qkv,
                                            float* __restrict__ osa){
    __shared__ __align__(16) float sK[100][32];
    __shared__ __align__(16) float sV[100][32];
    int h = blockIdx.x, b = blockIdx.y, l = blockIdx.z;
    int lb = l*4 + b;
    const float* qb = qkv + (size_t)lb*100*768;
    for (int idx = threadIdx.x; idx < 1600; idx += 128){
        int arr = (idx >= 800);
        int rem = arr ? idx - 800 : idx;
        int row = rem >> 3, qd = rem & 7;
        float4 v = *reinterpret_cast<const float4*>(
            qb + (size_t)row*768 + 256 + arr*256 + h*32 + qd*4);
        float* dstp = arr ? &sV[row][qd*4] : &sK[row][qd*4];
        *reinterpret_cast<float4*>(dstp) = v;
    }
    __syncthreads();
    int i = threadIdx.x;
    if (i < 100){
        float Q[32];
        const float4* qp4 = reinterpret_cast<const float4*>(qb + (size_t)i*768 + h*32);
#pragma unroll
        for (int qd = 0; qd < 8; qd++){
            float4 v = qp4[qd];
            Q[qd*4+0] = v.x; Q[qd*4+1] = v.y; Q[qd*4+2] = v.z; Q[qd*4+3] = v.w;
        }
        float m = -1e30f, s = 0.f, acc[32];
#pragma unroll
        for (int c = 0; c < 32; c++) acc[c] = 0.f;
        for (int j = 0; j < 100; j++){
            const float4* k4 = reinterpret_cast<const float4*>(sK[j]);
            float d = 0.f;
#pragma unroll
            for (int qd = 0; qd < 8; qd++){
                float4 kv = k4[qd];
                d = fmaf(Q[qd*4+0], kv.x, d); d = fmaf(Q[qd*4+1], kv.y, d);
                d = fmaf(Q[qd*4+2], kv.z, d); d = fmaf(Q[qd*4+3], kv.w, d);
            }
            d *= 0.17677669529663687f;
            const float4* v4 = reinterpret_cast<const float4*>(sV[j]);
            if (d > m){
                float f = __expf(m - d);
                m = d; s = fmaf(s, f, 1.f);
#pragma unroll
                for (int qd = 0; qd < 8; qd++){
                    float4 vv = v4[qd];
                    acc[qd*4+0] = fmaf(acc[qd*4+0], f, vv.x);
                    acc[qd*4+1] = fmaf(acc[qd*4+1], f, vv.y);
                    acc[qd*4+2] = fmaf(acc[qd*4+2], f, vv.z);
                    acc[qd*4+3] = fmaf(acc[qd*4+3], f, vv.w);
                }
            } else {
                float p = __expf(d - m);
                s += p;
#pragma unroll
                for (int qd = 0; qd < 8; qd++){
                    float4 vv = v4[qd];
                    acc[qd*4+0] = fmaf(p, vv.x, acc[qd*4+0]);
                    acc[qd*4+1] = fmaf(p, vv.y, acc[qd*4+1]);
                    acc[qd*4+2] = fmaf(p, vv.z, acc[qd*4+2]);
                    acc[qd*4+3] = fmaf(p, vv.w, acc[qd*4+3]);
                }
            }
        }
        float inv = 1.f / s;
        float* o = osa + (size_t)(lb*100 + i)*256 + h*32;
#pragma unroll
        for (int c = 0; c < 32; c++) o[c] = acc[c]*inv;
    }
}

// ---------------- cross-attention flash partials (cp.async pipelined) ----------------
__global__ void __launch_bounds__(128) k_cross(
    const float* __restrict__ qn, const float* __restrict__ Kg,
    const float* __restrict__ Vg, float* __restrict__ pm,
    float* __restrict__ ps, float* __restrict__ pacc)
{
    __shared__ __align__(16) float sKV[2][2][64][32];   // [buf][K/V][row][c]
    int ss = blockIdx.x, h = blockIdx.y, vb = blockIdx.z;
    int v = vb >> 2, b = vb & 3;
    int l = c_sl[ss];
    int Nl = c_N[l];
    int ck = c_ck[ss];
    int kbeg = c_sk[ss]*ck;
    int lb = l*4 + b;
    size_t kvbase = ((size_t)v*TOKV + c_off[l] + (size_t)b*Nl)*256 + h*32;
    const float* Kp = Kg + kvbase;
    const float* Vp = Vg + kvbase;
    int tid = threadIdx.x;
    uint32_t sbase = smem_u32(&sKV[0][0][0][0]);

    auto prefetch = [&](int kc, int buf){
        uint32_t stage = sbase + buf*16384;
#pragma unroll
        for (int it = 0; it < 8; it++){
            int idx = tid + it*128;
            int a = idx >> 9, rem = idx & 511;
            int row = rem >> 3, qd = rem & 7;
            const float* src = (a ? Vp : Kp) + (size_t)(kc + row)*256 + qd*4;
            cp16(stage + a*8192 + row*128 + qd*16, src);
        }
        cp_commit();
    };

    int i = tid;
    float Q[32];
    if (i < 100){
        const float4* qp4 = reinterpret_cast<const float4*>(
            qn + (size_t)(lb*100 + i)*256 + h*32);
#pragma unroll
        for (int qd = 0; qd < 8; qd++){
            float4 vq = qp4[qd];
            Q[qd*4+0] = vq.x; Q[qd*4+1] = vq.y; Q[qd*4+2] = vq.z; Q[qd*4+3] = vq.w;
        }
    }
    float m = -1e30f, s = 0.f, acc[32];
#pragma unroll
    for (int c = 0; c < 32; c++) acc[c] = 0.f;

    int nchunks = ck >> 6;
    prefetch(kbeg, 0);
    for (int cki = 0; cki < nchunks; cki++){
        int buf = cki & 1;
        if (cki + 1 < nchunks){ prefetch(kbeg + (cki+1)*64, buf ^ 1); cp_wait<1>(); }
        else                  { cp_wait<0>(); }
        __syncthreads();
        if (i < 100){
            for (int j = 0; j < 64; j++){
                const float4* k4 = reinterpret_cast<const float4*>(sKV[buf][0][j]);
                float d = 0.f;
#pragma unroll
                for (int qd = 0; qd < 8; qd++){
                    float4 kv = k4[qd];
                    d = fmaf(Q[qd*4+0], kv.x, d); d = fmaf(Q[qd*4+1], kv.y, d);
                    d = fmaf(Q[qd*4+2], kv.z, d); d = fmaf(Q[qd*4+3], kv.w, d);
                }
                d *= 0.17677669529663687f;
                const float4* v4 = reinterpret_cast<const float4*>(sKV[buf][1][j]);
                if (d > m){
                    float f = __expf(m - d);
                    m = d; s = fmaf(s, f, 1.f);
#pragma unroll
                    for (int qd = 0; qd < 8; qd++){
                        float4 vv = v4[qd];
                        acc[qd*4+0] = fmaf(acc[qd*4+0], f, vv.x);
                        acc[qd*4+1] = fmaf(acc[qd*4+1], f, vv.y);
                        acc[qd*4+2] = fmaf(acc[qd*4+2], f, vv.z);
                        acc[qd*4+3] = fmaf(acc[qd*4+3], f, vv.w);
                    }
                } else {
                    float p = __expf(d - m);
                    s += p;
#pragma unroll
                    for (int qd = 0; qd < 8; qd++){
                        float4 vv = v4[qd];
                        acc[qd*4+0] = fmaf(p, vv.x, acc[qd*4+0]);
                        acc[qd*4+1] = fmaf(p, vv.y, acc[qd*4+1]);
                        acc[qd*4+2] = fmaf(p, vv.z, acc[qd*4+2]);
                        acc[qd*4+3] = fmaf(p, vv.w, acc[qd*4+3]);
                    }
                }
            }
        }
        __syncthreads();
    }
    if (i < 100){
        int slot = (vb*8 + h)*8 + ss;
        pm[slot*100 + i] = m;
        ps[slot*100 + i] = s;
        float* pa = pacc + (size_t)(slot*100 + i)*32;
#pragma unroll
        for (int c = 0; c < 32; c++) pa[c] = acc[c];
    }
}

__global__ void __launch_bounds__(128) k_combine(
    const float* __restrict__ pm, const float* __restrict__ ps,
    const float* __restrict__ pacc, float* __restrict__ ocr)
{
    int l = blockIdx.x, h = blockIdx.y, vb = blockIdx.z;
    int i = threadIdx.x;
    if (i >= 100) return;
    int S = c_S[l], s0 = c_s0[l];
    int base = (vb*8 + h)*8 + s0;
    float M = -1e30f;
    for (int k = 0; k < S; k++) M = fmaxf(M, pm[(base + k)*100 + i]);
    float Ss = 0.f, acc[32];
#pragma unroll
    for (int c = 0; c < 32; c++) acc[c] = 0.f;
    for (int k = 0; k < S; k++){
        int slot = base + k;
        float f = __expf(pm[slot*100 + i] - M);
        Ss = fmaf(ps[slot*100 + i], f, Ss);
        const float* pa = pacc + (size_t)(slot*100 + i)*32;
#pragma unroll
        for (int c = 0; c < 32; c++) acc[c] = fmaf(pa[c], f, acc[c]);
    }
    float inv = 1.f / Ss;
    int v = vb >> 2, b = vb & 3;
    int lb = l*4 + b;
    float* o = ocr + (size_t)v*409600 + (size_t)(lb*100 + i)*256 + h*32;
#pragma unroll
    for (int c = 0; c < 32; c++) o[c] = acc[c]*inv;
}

// ---- matching score + both softmaxes, one block per lb ----
// ms computed into smem, then row softmax -> wr, col softmax -> wc.
__global__ void __launch_bounds__(256) k_matchsm(const float* __restrict__ q12,
                                                 float* __restrict__ wr,
                                                 float* __restrict__ wc){
    extern __shared__ float buf[];          // >= 10100 floats
    float* sA = buf;                        // [100][33]
    float* sB = buf + 3300;                 // [100][33]
    int lb = blockIdx.x;
    int tid = threadIdx.x;
    int tx = tid & 15, ty = tid >> 4;
    const float* q1 = q12 + (size_t)lb*25600;
    const float* q2 = q12 + 409600 + (size_t)lb*25600;
    float acc[7][7];
#pragma unroll
    for (int a = 0; a < 7; a++)
#pragma unroll
        for (int bq = 0; bq < 7; bq++) acc[a][bq] = 0.f;
    for (int k0 = 0; k0 < 256; k0 += 32){
        __syncthreads();
        for (int idx = tid; idx < 3200; idx += 256){
            int r = idx >> 5, kk = idx & 31;
            sA[r*33 + kk] = q1[(size_t)r*256 + k0 + kk];
            sB[r*33 + kk] = q2[(size_t)r*256 + k0 + kk];
        }
        __syncthreads();
        for (int kk = 0; kk < 32; kk++){
            float a[7], b[7];
#pragma unroll
            for (int ii = 0; ii < 7; ii++){
                int i = ty + 16*ii;
                a[ii] = (i < 100) ? sA[i*33 + kk] : 0.f;
            }
#pragma unroll
            for (int jj = 0; jj < 7; jj++){
                int j = tx + 16*jj;
                b[jj] = (j < 100) ? sB[j*33 + kk] : 0.f;
            }
#pragma unroll
            for (int ii = 0; ii < 7; ii++)
#pragma unroll
                for (int jj = 0; jj < 7; jj++) acc[ii][jj] = fmaf(a[ii], b[jj], acc[ii][jj]);
        }
    }
    __syncthreads();                        // done with sA/sB; reuse buf as ms[100][101]
#pragma unroll
    for (int ii = 0; ii < 7; ii++){
        int i = ty + 16*ii;
        if (i < 100){
#pragma unroll
            for (int jj = 0; jj < 7; jj++){
                int j = tx + 16*jj;
                if (j < 100) buf[i*101 + j] = acc[ii][jj];
            }
        }
    }
    __syncthreads();
    int w = tid >> 5, lane = tid & 31;
    // row softmax -> wr[i][j]
    for (int r = w; r < 100; r += 8){
        float v0 = buf[r*101 + lane];
        float v1 = buf[r*101 + 32 + lane];
        float v2 = buf[r*101 + 64 + lane];
        float v3 = (lane < 4) ? buf[r*101 + 96 + lane] : -1e30f;
        float M = warpMax(fmaxf(fmaxf(v0, v1), fmaxf(v2, v3)));
        float p0 = __expf(v0 - M), p1 = __expf(v1 - M), p2 = __expf(v2 - M);
        float p3 = (lane < 4) ? __expf(v3 - M) : 0.f;
        float S = warpSum(p0 + p1 + p2 + p3);
        float inv = 1.f / S;
        float* o = wr + (size_t)lb*10000 + r*100;
        o[lane] = p0*inv; o[32 + lane] = p1*inv; o[64 + lane] = p2*inv;
        if (lane < 4) o[96 + lane] = p3*inv;
    }
    // col softmax -> wc[j][i]
    for (int cc = w; cc < 100; cc += 8){
        float v0 = buf[lane*101 + cc];
        float v1 = buf[(32 + lane)*101 + cc];
        float v2 = buf[(64 + lane)*101 + cc];
        float v3 = (lane < 4) ? buf[(96 + lane)*101 + cc] : -1e30f;
        float M = warpMax(fmaxf(fmaxf(v0, v1), fmaxf(v2, v3)));
        float p0 = __expf(v0 - M), p1 = __expf(v1 - M), p2 = __expf(v2 - M);
        float p3 = (lane < 4) ? __expf(v3 - M) : 0.f;
        float S = warpSum(p0 + p1 + p2 + p3);
        float inv = 1.f / S;
        float* o = wc + (size_t)lb*10000 + cc;
        o[lane*100] = p0*inv; o[(32 + lane)*100] = p1*inv; o[(64 + lane)*100] = p2*inv;
        if (lane < 4) o[(96 + lane)*100] = p3*inv;
    }
}

// -------- fuse (4 queries/block): t = qsa+q1+q2+Wr@q2+Wc^T@q1; softmax over c ----
__global__ void __launch_bounds__(256) k_fuse(
    const float* __restrict__ qsa, const float* __restrict__ q12,
    const float* __restrict__ wr, const float* __restrict__ wc,
    float* __restrict__ outp)
{
    __shared__ float swr[4][100];
    __shared__ float swc[4][100];
    __shared__ float sh[32];
    int i0 = blockIdx.x * 4, lb = blockIdx.y, c = threadIdx.x;
    const float* q1 = q12 + (size_t)lb*25600;
    const float* q2 = q12 + 409600 + (size_t)lb*25600;
    for (int idx = c; idx < 400; idx += 256){
        int ii = idx / 100, j = idx % 100;
        swr[ii][j] = wr[(size_t)lb*10000 + (i0+ii)*100 + j];
        swc[ii][j] = wc[(size_t)lb*10000 + j*100 + (i0+ii)];
    }
    __syncthreads();
    float acc[4];
#pragma unroll
    for (int ii = 0; ii < 4; ii++)
        acc[ii] = qsa[(size_t)(lb*100 + i0+ii)*256 + c]
                + q1[(size_t)(i0+ii)*256 + c] + q2[(size_t)(i0+ii)*256 + c];
    for (int j = 0; j < 100; j++){
        float q1v = q1[(size_t)j*256 + c];
        float q2v = q2[(size_t)j*256 + c];
#pragma unroll
        for (int ii = 0; ii < 4; ii++){
            acc[ii] = fmaf(swr[ii][j], q2v, acc[ii]);
            acc[ii] = fmaf(swc[ii][j], q1v, acc[ii]);
        }
    }
#pragma unroll
    for (int ii = 0; ii < 4; ii++){
        float M = blockMax(acc[ii], sh);
        float e = __expf(acc[ii] - M);
        float S = blockSum(e, sh);
        outp[(size_t)(lb*100 + i0+ii)*256 + c] = e / S;
    }
}

// ---------------- host ----------------
extern "C" void kernel_launch(void* const* d_in, const int* in_sizes, int n_in,
                              void* d_out, int out_size)
{
    float* arena;   cudaGetSymbolAddress((void**)&arena, g_buf);
    float* kvbuf;   cudaGetSymbolAddress((void**)&kvbuf, g_kv);
    __nv_bfloat16 *ahi, *alo, *whi, *wlo;
    cudaGetSymbolAddress((void**)&ahi, g_ahi);
    cudaGetSymbolAddress((void**)&alo, g_alo);
    cudaGetSymbolAddress((void**)&whi, g_whi);
    cudaGetSymbolAddress((void**)&wlo, g_wlo);
    float* bkv;     cudaGetSymbolAddress((void**)&bkv, g_bkv);

    float* q    = arena;                 // 409600
    float* qkv  = arena + 409600;        // 1228800
    float* osa  = arena + 1638400;       // 409600
    float* qsa  = arena + 2048000;       // 409600
    float* wqf  = arena + 2457600;       // 393216
    float* bqf  = arena + 2850816;       // 1536
    float* qn   = arena + 2867200;       // 409600
    float* ocr  = arena + 3276800;       // 819200
    float* q12  = arena + 4096000;       // 819200
    float* wr   = arena + 4915200;       // 160000
    float* wc   = arena + 5075200;       // 160000
    float* pm   = arena + 5235200;       // 51200
    float* ps   = arena + 5286400;       // 51200
    float* pacc = arena + 5337600;       // 1638400

    FeatPtrs fp;
    for (int i = 0; i < 8; i++) fp.p[i] = (const float*)d_in[i];
    const float* qe   = (const float*)d_in[8];
    const float* ng   = (const float*)d_in[9];
    const float* nb   = (const float*)d_in[10];
    const float* wq   = (const float*)d_in[11];
    const float* wk   = (const float*)d_in[12];
    const float* wv   = (const float*)d_in[13];
    const float* wp   = (const float*)d_in[14];
    const float* bp   = (const float*)d_in[15];
    const float* wqkv = (const float*)d_in[16];
    const float* swp  = (const float*)d_in[17];
    const float* sbp  = (const float*)d_in[18];

    cudaFuncSetAttribute(k_kvgemm, cudaFuncAttributeMaxDynamicSharedMemorySize, 131072);

    k_tok_ln<<<dim3(680, 2), 256>>>(fp, ahi, alo);
    k_prep_w<<<12, 256>>>(wk, wv, ng, nb, whi, wlo, bkv);
    k_prep_wq<<<6, 256>>>(wq, ng, nb, wqf, bqf);
    k_init_q<<<1600, 256>>>(qe, q);
    k_kvgemm<<<dim3(340, 2, 12), 256, 131072>>>(ahi, alo, whi, wlo, bkv, kvbuf);

    for (int d = 0; d < 6; d++){
        k_gemm64<<<dim3(25, 6), 256>>>(q, wqkv + (size_t)d*256*768,
                                       nullptr, qkv, 1600, 768, 0);
        k_sa<<<dim3(8, 4, 4), 128>>>(qkv, osa);
        k_gemm64<<<dim3(25, 2), 256>>>(osa, swp + (size_t)d*65536,
                                       sbp + d*256, qsa, 1600, 256, 0);
        k_gemm64<<<dim3(25, 2), 256>>>(qsa, wqf + (size_t)d*65536,
                                       bqf + d*256, qn, 1600, 256, 1);
        k_cross<<<dim3(8, 8, 8), 128>>>(qn, kvbuf + (size_t)(2*d)*KVSZ,
                                        kvbuf + (size_t)(2*d+1)*KVSZ, pm, ps, pacc);
        k_combine<<<dim3(4, 8, 8), 128>>>(pm, ps, pacc, ocr);
        k_gemm64<<<dim3(50, 2), 256>>>(ocr, wp + (size_t)d*65536,
                                       bp + d*256, q12, 3200, 256, 0);
        k_matchsm<<<16, 256, 10100*sizeof(float)>>>(q12, wr, wc);
        k_fuse<<<dim3(25, 16), 256>>>(qsa, q12, wr, wc,
                                      (d == 5) ? (float*)d_out : q);
    }
}

// round 10
// speedup vs baseline: 1.4663x; 1.0662x over previous
#include <cuda_runtime.h>
#include <cuda_bf16.h>
#include <cstdint>
#include <math.h>

#define TOKV 21760            // per-view feature tokens: 4*(4096+1024+256+64)
#define AROWS 43520           // 2 views
#define KVSZ  11141120        // 43520*256

__constant__ int c_N[4]   = {4096, 1024, 256, 64};
__constant__ int c_off[4] = {0, 16384, 20480, 21504};
// 22 cross-attn split slots (256-key chunks; level 3 has 64)
__constant__ int c_sl[22] = {0,0,0,0,0,0,0,0,0,0,0,0,0,0,0,0, 1,1,1,1, 2, 3};
__constant__ int c_sk[22] = {0,1,2,3,4,5,6,7,8,9,10,11,12,13,14,15, 0,1,2,3, 0, 0};
__constant__ int c_ck[22] = {256,256,256,256,256,256,256,256,256,256,256,256,256,256,256,256,
                             256,256,256,256, 256, 64};
__constant__ int c_S[4]  = {16,4,1,1};
__constant__ int c_s0[4] = {0,16,20,21};

// ---- device scratch (allocations forbidden) ----
__device__ float g_kv[12*KVSZ];                  // K/V for all 6 depths (535 MB)
__device__ __nv_bfloat16 g_ahi[AROWS*256];
__device__ __nv_bfloat16 g_alo[AROWS*256];
__device__ __nv_bfloat16 g_whi[12*256*256];
__device__ __nv_bfloat16 g_wlo[12*256*256];
__device__ float g_bkv[12*256];
__device__ float g_buf[12000000];

struct FeatPtrs { const float* p[8]; };

// ---------------- PTX helpers ----------------
__device__ __forceinline__ uint32_t smem_u32(const void* p){
    uint32_t a;
    asm("{ .reg .u64 t; cvta.to.shared.u64 t, %1; cvt.u32.u64 %0, t; }" : "=r"(a) : "l"(p));
    return a;
}
__device__ __forceinline__ void cp16(uint32_t s, const void* g){
    asm volatile("cp.async.cg.shared.global [%0], [%1], 16;" :: "r"(s), "l"(g) : "memory");
}
__device__ __forceinline__ void cp_commit(){
    asm volatile("cp.async.commit_group;" ::: "memory");
}
template<int N>
__device__ __forceinline__ void cp_wait(){
    asm volatile("cp.async.wait_group %0;" :: "n"(N) : "memory");
}
__device__ __forceinline__ void ldsm4(uint32_t* r, uint32_t a){
    asm volatile("ldmatrix.sync.aligned.m8n8.x4.shared.b16 {%0,%1,%2,%3}, [%4];"
                 : "=r"(r[0]), "=r"(r[1]), "=r"(r[2]), "=r"(r[3]) : "r"(a));
}
__device__ __forceinline__ void mma16816(float* c, const uint32_t* a,
                                         uint32_t b0, uint32_t b1){
    asm volatile(
        "mma.sync.aligned.m16n8k16.row.col.f32.bf16.bf16.f32 "
        "{%0,%1,%2,%3}, {%4,%5,%6,%7}, {%8,%9}, {%0,%1,%2,%3};"
        : "+f"(c[0]), "+f"(c[1]), "+f"(c[2]), "+f"(c[3])
        : "r"(a[0]), "r"(a[1]), "r"(a[2]), "r"(a[3]), "r"(b0), "r"(b1));
}

// ---------------- reductions ----------------
__device__ __forceinline__ float warpSum(float v){
#pragma unroll
    for (int o = 16; o > 0; o >>= 1) v += __shfl_xor_sync(0xffffffffu, v, o);
    return v;
}
__device__ __forceinline__ float warpMax(float v){
#pragma unroll
    for (int o = 16; o > 0; o >>= 1) v = fmaxf(v, __shfl_xor_sync(0xffffffffu, v, o));
    return v;
}
__device__ __forceinline__ float blockSum(float v, float* sh){
    int lane = threadIdx.x & 31, w = threadIdx.x >> 5;
    int nw = blockDim.x >> 5;
    __syncthreads();
    v = warpSum(v);
    if (lane == 0) sh[w] = v;
    __syncthreads();
    if (w == 0){
        float r = (threadIdx.x < nw) ? sh[threadIdx.x] : 0.f;
        r = warpSum(r);
        if (lane == 0) sh[0] = r;
    }
    __syncthreads();
    return sh[0];
}
__device__ __forceinline__ float blockMax(float v, float* sh){
    int lane = threadIdx.x & 31, w = threadIdx.x >> 5;
    int nw = blockDim.x >> 5;
    __syncthreads();
    v = warpMax(v);
    if (lane == 0) sh[w] = v;
    __syncthreads();
    if (w == 0){
        float r = (threadIdx.x < nw) ? sh[threadIdx.x] : -1e30f;
        r = warpMax(r);
        if (lane == 0) sh[0] = r;
    }
    __syncthreads();
    return sh[0];
}

// ---- tokenize + LN normalization -> bf16 hi/lo (coalesced; affine folded into W) ----
__global__ void __launch_bounds__(256) k_tok_ln(FeatPtrs fp,
    __nv_bfloat16* __restrict__ ahi, __nv_bfloat16* __restrict__ alo)
{
    __shared__ float s[256][33];
    __shared__ float ps[8][32], pq[8][32];
    __shared__ float mean[32], rinv[32];
    int r = blockIdx.x, v = blockIdx.y;
    int l = (r < 512) ? 0 : (r < 640) ? 1 : (r < 672) ? 2 : 3;
    int off32 = (l == 0) ? 0 : (l == 1) ? 512 : (l == 2) ? 640 : 672;
    int Nl = c_N[l];
    int idx = r - off32;
    int tpb = Nl >> 5;
    int b = idx / tpb, t0 = (idx % tpb) * 32;
    const float* f = fp.p[v*4 + l];
    int g = threadIdx.x >> 5, t = threadIdx.x & 31;
    for (int cc = g; cc < 256; cc += 8)
        s[cc][t] = f[((size_t)(b*256 + cc))*Nl + t0 + t];
    __syncthreads();
    float sx = 0.f, sq = 0.f;
#pragma unroll
    for (int k = 0; k < 32; k++){
        float x = s[g*32 + k][t];
        sx += x; sq = fmaf(x, x, sq);
    }
    ps[g][t] = sx; pq[g][t] = sq;
    __syncthreads();
    if (threadIdx.x < 32){
        float m = 0.f, qq = 0.f;
#pragma unroll
        for (int gg = 0; gg < 8; gg++){ m += ps[gg][threadIdx.x]; qq += pq[gg][threadIdx.x]; }
        m *= (1.f/256.f);
        float var = qq*(1.f/256.f) - m*m;
        mean[threadIdx.x] = m;
        rinv[threadIdx.x] = rsqrtf(var + 1e-5f);
    }
    __syncthreads();
    int c = threadIdx.x;
    size_t rowbase = (size_t)v*TOKV + c_off[l] + (size_t)b*Nl + t0;
    for (int tt = 0; tt < 32; tt++){
        float val = (s[c][tt] - mean[tt]) * rinv[tt];
        __nv_bfloat16 h = __float2bfloat16(val);
        ahi[(rowbase + tt)*256 + c] = h;
        alo[(rowbase + tt)*256 + c] = __float2bfloat16(val - __bfloat162float(h));
    }
}

// ---- prep KV weights: Wt[n][k] = g[k]*W[k][n] bf16 hi/lo; bias'[n] = b@W ----
__global__ void __launch_bounds__(256) k_prep_w(
    const float* __restrict__ wk, const float* __restrict__ wv,
    const float* __restrict__ ng, const float* __restrict__ nb,
    __nv_bfloat16* __restrict__ whi, __nv_bfloat16* __restrict__ wlo,
    float* __restrict__ bkv)
{
    int s = blockIdx.x, n = threadIdx.x;
    int d = s >> 1;
    const float* W = ((s & 1) ? wv : wk) + (size_t)d*65536;
    const float* g = ng + d*256;
    const float* b = nb + d*256;
    float bias = 0.f;
    size_t obase = ((size_t)s*256 + n)*256;
    for (int k = 0; k < 256; k++){
        float w0 = W[k*256 + n];
        bias = fmaf(b[k], w0, bias);
        float w = g[k]*w0;
        __nv_bfloat16 h = __float2bfloat16(w);
        whi[obase + k] = h;
        wlo[obase + k] = __float2bfloat16(w - __bfloat162float(h));
    }
    bkv[s*256 + n] = bias;
}

// ---- prep Q weights (fp32): wqf[k][n] = g[k]*wq[k][n]; bqf[n] = b@wq ----
__global__ void __launch_bounds__(256) k_prep_wq(
    const float* __restrict__ wq, const float* __restrict__ ng,
    const float* __restrict__ nb, float* __restrict__ wqf,
    float* __restrict__ bqf)
{
    int d = blockIdx.x, n = threadIdx.x;
    const float* W = wq + (size_t)d*65536;
    const float* g = ng + d*256;
    const float* b = nb + d*256;
    float bias = 0.f;
    for (int k = 0; k < 256; k++){
        float w0 = W[k*256 + n];
        bias = fmaf(b[k], w0, bias);
        wqf[(size_t)d*65536 + k*256 + n] = g[k]*w0;
    }
    bqf[d*256 + n] = bias;
}

__global__ void k_init_q(const float* __restrict__ qe, float* __restrict__ q){
    int row = blockIdx.x, c = threadIdx.x;
    q[(size_t)row*256 + c] = qe[(row % 100)*256 + c];
}

// ---- mma.sync KV GEMM, 512 threads: C[slot][43520,256] = A(hi/lo)@Wt(hi/lo)^T + bias
__global__ void __launch_bounds__(512) k_kvgemm(
    const __nv_bfloat16* __restrict__ Ahi, const __nv_bfloat16* __restrict__ Alo,
    const __nv_bfloat16* __restrict__ Whi, const __nv_bfloat16* __restrict__ Wlo,
    const float* __restrict__ bkv, float* __restrict__ Cbuf)
{
    extern __shared__ char sm[];
    uint32_t sb = smem_u32(sm);
    int tid = threadIdx.x, lane = tid & 31, warp = tid >> 5;
    int mt = blockIdx.x, nh = blockIdx.y, slot = blockIdx.z;
    size_t arow0 = (size_t)mt * 128;
    const __nv_bfloat16* wh = Whi + (size_t)slot*65536 + (size_t)nh*128*256;
    const __nv_bfloat16* wl = Wlo + (size_t)slot*65536 + (size_t)nh*128*256;

    int wm = warp >> 2, wn = warp & 3;           // warp tile: 32m x 32n

    float acc[2][4][4];
#pragma unroll
    for (int mi = 0; mi < 2; mi++)
#pragma unroll
        for (int ni = 0; ni < 4; ni++)
#pragma unroll
            for (int k = 0; k < 4; k++) acc[mi][ni][k] = 0.f;

    auto prefetch = [&](int ck, int buf){
        uint32_t stage = sb + buf*65536;
#pragma unroll
        for (int it = 0; it < 2; it++){
            int i = tid + it*512;
            int row = i >> 3, g = i & 7;
            uint32_t so = stage + row*128 + (((g ^ (row & 7)) << 4));
            cp16(so,         Ahi + (arow0 + row)*256 + ck*64 + g*8);
            cp16(so + 16384, Alo + (arow0 + row)*256 + ck*64 + g*8);
            cp16(so + 32768, wh + row*256 + ck*64 + g*8);
            cp16(so + 49152, wl + row*256 + ck*64 + g*8);
        }
        cp_commit();
    };

    prefetch(0, 0);

    for (int ck = 0; ck < 4; ck++){
        int buf = ck & 1;
        if (ck + 1 < 4){ prefetch(ck + 1, (ck + 1) & 1); cp_wait<1>(); }
        else           { cp_wait<0>(); }
        __syncthreads();

        uint32_t stage = sb + buf*65536;
#pragma unroll
        for (int k16 = 0; k16 < 4; k16++){
            int msel = lane >> 3;
            int rsub = (msel & 1)*8 + (lane & 7);
            int gg   = k16*2 + (msel >> 1);
            uint32_t ah[2][4], al[2][4];
#pragma unroll
            for (int mi = 0; mi < 2; mi++){
                int r = wm*32 + mi*16 + rsub;
                uint32_t ad = stage + r*128 + (((gg ^ (r & 7)) << 4));
                ldsm4(ah[mi], ad);
                ldsm4(al[mi], ad + 16384);
            }
            uint32_t bh[2][4], bl[2][4];
#pragma unroll
            for (int nj = 0; nj < 2; nj++){
                int r = wn*32 + nj*16 + rsub;
                uint32_t ad = stage + 32768 + r*128 + (((gg ^ (r & 7)) << 4));
                ldsm4(bh[nj], ad);
                ldsm4(bl[nj], ad + 16384);
            }
#pragma unroll
            for (int mi = 0; mi < 2; mi++)
#pragma unroll
                for (int ni = 0; ni < 4; ni++){
                    int nj = ni >> 1, sel = ni & 1;
                    mma16816(acc[mi][ni], ah[mi], bh[nj][sel], bh[nj][2+sel]);
                    mma16816(acc[mi][ni], ah[mi], bl[nj][sel], bl[nj][2+sel]);
                    mma16816(acc[mi][ni], al[mi], bh[nj][sel], bh[nj][2+sel]);
                }
        }
        __syncthreads();
    }

    // epilogue: stage fp32 tile in smem (stride 132), stream out coalesced
    float* st = reinterpret_cast<float*>(sm);
#pragma unroll
    for (int mi = 0; mi < 2; mi++)
#pragma unroll
        for (int ni = 0; ni < 4; ni++){
            int r0 = wm*32 + mi*16 + (lane >> 2);
            int c0 = wn*32 + ni*8 + (lane & 3)*2;
            *reinterpret_cast<float2*>(st + r0*132 + c0)       = make_float2(acc[mi][ni][0], acc[mi][ni][1]);
            *reinterpret_cast<float2*>(st + (r0 + 8)*132 + c0) = make_float2(acc[mi][ni][2], acc[mi][ni][3]);
        }
    __syncthreads();
    const float4* bp4 = reinterpret_cast<const float4*>(bkv + slot*256 + nh*128);
    float* dst = Cbuf + (size_t)slot*KVSZ + arow0*256 + nh*128;
#pragma unroll
    for (int it = 0; it < 8; it++){
        int i = tid + it*512;
        int row = i >> 5, q = i & 31;
        float4 v = *reinterpret_cast<float4*>(st + row*132 + q*4);
        float4 bb = bp4[q];
        v.x += bb.x; v.y += bb.y; v.z += bb.z; v.w += bb.w;
        *reinterpret_cast<float4*>(dst + (size_t)row*256 + q*4) = v;
    }
}

// -------- SIMT SGEMM 64x128 tile: C = A[M,256] @ W[256,N] (+bias) --------
__global__ void __launch_bounds__(256) k_gemm64(
    const float* __restrict__ A, const float* __restrict__ W,
    const float* __restrict__ bias, float* __restrict__ Cout,
    int M, int N)
{
    __shared__ __align__(16) float As[8][64];
    __shared__ __align__(16) float Bs[8][128];
    int tid = threadIdx.x;
    int m0 = blockIdx.x * 64, n0 = blockIdx.y * 128;

    int tx = tid & 15, ty = tid >> 4;
    float acc[4][8];
#pragma unroll
    for (int i = 0; i < 4; i++)
#pragma unroll
        for (int j = 0; j < 8; j++) acc[i][j] = 0.f;

    int arow = tid >> 1, acol = (tid & 1)*4;
    int brow = tid >> 5, bcol = (tid & 31)*4;

    for (int k0 = 0; k0 < 256; k0 += 8){
        if (tid < 128){
            float4 av = *reinterpret_cast<const float4*>(A + (size_t)(m0 + arow)*256 + k0 + acol);
            As[acol+0][arow] = av.x; As[acol+1][arow] = av.y;
            As[acol+2][arow] = av.z; As[acol+3][arow] = av.w;
        }
        *reinterpret_cast<float4*>(&Bs[brow][bcol]) =
            *reinterpret_cast<const float4*>(W + (size_t)(k0 + brow)*N + n0 + bcol);
        __syncthreads();
#pragma unroll
        for (int kk = 0; kk < 8; kk++){
            float a[4], b[8];
            *reinterpret_cast<float4*>(a)     = *reinterpret_cast<float4*>(&As[kk][ty*4]);
            *reinterpret_cast<float4*>(b)     = *reinterpret_cast<float4*>(&Bs[kk][tx*8]);
            *reinterpret_cast<float4*>(b + 4) = *reinterpret_cast<float4*>(&Bs[kk][tx*8 + 4]);
#pragma unroll
            for (int i = 0; i < 4; i++)
#pragma unroll
                for (int j = 0; j < 8; j++) acc[i][j] = fmaf(a[i], b[j], acc[i][j]);
        }
        __syncthreads();
    }
#pragma unroll
    for (int i = 0; i < 4; i++){
        int gm = m0 + ty*4 + i;
#pragma unroll
        for (int j = 0; j < 8; j += 4){
            int gn = n0 + tx*8 + j;
            float4 o;
            o.x = acc[i][j+0]; o.y = acc[i][j+1]; o.z = acc[i][j+2]; o.w = acc[i][j+3];
            if (bias){
                o.x += bias[gn+0]; o.y += bias[gn+1];
                o.z += bias[gn+2]; o.w += bias[gn+3];
            }
            *reinterpret_cast<float4*>(Cout + (size_t)gm*N + gn) = o;
        }
    }
}

// ---- fused qsa = osa@swp+sbp ; qn = LN(qsa)@wqf+bqf ; 32-row tiles ----
__global__ void __launch_bounds__(256) k_sa2(
    const float* __restrict__ osa, const float* __restrict__ swp,
    const float* __restrict__ sbp, const float* __restrict__ wqf,
    const float* __restrict__ bqf, float* __restrict__ qsa,
    float* __restrict__ qn)
{
    __shared__ __align__(16) float X[32][260];
    __shared__ __align__(16) float As[8][32];
    __shared__ __align__(16) float Bs[8][256];
    __shared__ float redS[32][8], redQ[32][8];
    __shared__ float s_mean[32], s_rinv[32];
    int tid = threadIdx.x;
    int m0 = blockIdx.x * 32;
    int tx = tid & 31, ty = tid >> 5;
    int arow = tid >> 1, acol = (tid & 1)*4;

    float acc[4][8];
#pragma unroll
    for (int i = 0; i < 4; i++)
#pragma unroll
        for (int j = 0; j < 8; j++) acc[i][j] = 0.f;

    // GEMM1: qsa tile = osa @ swp + sbp
    for (int k0 = 0; k0 < 256; k0 += 8){
        if (tid < 64){
            float4 av = *reinterpret_cast<const float4*>(osa + (size_t)(m0 + arow)*256 + k0 + acol);
            As[acol+0][arow] = av.x; As[acol+1][arow] = av.y;
            As[acol+2][arow] = av.z; As[acol+3][arow] = av.w;
        }
#pragma unroll
        for (int it = 0; it < 2; it++){
            int idx = tid + it*256;
            int brow = idx >> 6, bcol = (idx & 63)*4;
            *reinterpret_cast<float4*>(&Bs[brow][bcol]) =
                *reinterpret_cast<const float4*>(swp + (size_t)(k0 + brow)*256 + bcol);
        }
        __syncthreads();
#pragma unroll
        for (int kk = 0; kk < 8; kk++){
            float a[4], b[8];
            *reinterpret_cast<float4*>(a)     = *reinterpret_cast<float4*>(&As[kk][ty*4]);
            *reinterpret_cast<float4*>(b)     = *reinterpret_cast<float4*>(&Bs[kk][tx*8]);
            *reinterpret_cast<float4*>(b + 4) = *reinterpret_cast<float4*>(&Bs[kk][tx*8 + 4]);
#pragma unroll
            for (int i = 0; i < 4; i++)
#pragma unroll
                for (int j = 0; j < 8; j++) acc[i][j] = fmaf(a[i], b[j], acc[i][j]);
        }
        __syncthreads();
    }
#pragma unroll
    for (int i = 0; i < 4; i++){
        int row = ty*4 + i;
#pragma unroll
        for (int j = 0; j < 8; j += 4){
            int n = tx*8 + j;
            float4 o;
            o.x = acc[i][j+0] + sbp[n+0]; o.y = acc[i][j+1] + sbp[n+1];
            o.z = acc[i][j+2] + sbp[n+2]; o.w = acc[i][j+3] + sbp[n+3];
            *reinterpret_cast<float4*>(qsa + (size_t)(m0 + row)*256 + n) = o;
            *reinterpret_cast<float4*>(&X[row][n]) = o;
        }
    }
    __syncthreads();
    // LN stats per row
    {
        int row = tid >> 3, sub = tid & 7;
        float sx = 0.f, sq = 0.f;
#pragma unroll
        for (int k = 0; k < 32; k++){
            float x = X[row][sub*32 + k];
            sx += x; sq = fmaf(x, x, sq);
        }
        redS[row][sub] = sx; redQ[row][sub] = sq;
    }
    __syncthreads();
    if (tid < 32){
        float m = 0.f, q2 = 0.f;
#pragma unroll
        for (int j = 0; j < 8; j++){ m += redS[tid][j]; q2 += redQ[tid][j]; }
        m *= (1.f/256.f);
        float var = q2*(1.f/256.f) - m*m;
        s_mean[tid] = m;
        s_rinv[tid] = rsqrtf(var + 1e-5f);
    }
    __syncthreads();

    // GEMM2: qn tile = LNrows(X) @ wqf + bqf
#pragma unroll
    for (int i = 0; i < 4; i++)
#pragma unroll
        for (int j = 0; j < 8; j++) acc[i][j] = 0.f;
    for (int k0 = 0; k0 < 256; k0 += 8){
        if (tid < 64){
            float m = s_mean[arow], ri = s_rinv[arow];
            As[acol+0][arow] = (X[arow][k0+acol+0] - m)*ri;
            As[acol+1][arow] = (X[arow][k0+acol+1] - m)*ri;
            As[acol+2][arow] = (X[arow][k0+acol+2] - m)*ri;
            As[acol+3][arow] = (X[arow][k0+acol+3] - m)*ri;
        }
#pragma unroll
        for (int it = 0; it < 2; it++){
            int idx = tid + it*256;
            int brow = idx >> 6, bcol = (idx & 63)*4;
            *reinterpret_cast<float4*>(&Bs[brow][bcol]) =
                *reinterpret_cast<const float4*>(wqf + (size_t)(k0 + brow)*256 + bcol);
        }
        __syncthreads();
#pragma unroll
        for (int kk = 0; kk < 8; kk++){
            float a[4], b[8];
            *reinterpret_cast<float4*>(a)     = *reinterpret_cast<float4*>(&As[kk][ty*4]);
            *reinterpret_cast<float4*>(b)     = *reinterpret_cast<float4*>(&Bs[kk][tx*8]);
            *reinterpret_cast<float4*>(b + 4) = *reinterpret_cast<float4*>(&Bs[kk][tx*8 + 4]);
#pragma unroll
            for (int i = 0; i < 4; i++)
#pragma unroll
                for (int j = 0; j < 8; j++) acc[i][j] = fmaf(a[i], b[j], acc[i][j]);
        }
        __syncthreads();
    }
#pragma unroll
    for (int i = 0; i < 4; i++){
        int row = ty*4 + i;
#pragma unroll
        for (int j = 0; j < 8; j += 4){
            int n = tx*8 + j;
            float4 o;
            o.x = acc[i][j+0] + bqf[n+0]; o.y = acc[i][j+1] + bqf[n+1];
            o.z = acc[i][j+2] + bqf[n+2]; o.w = acc[i][j+3] + bqf[n+3];
            *reinterpret_cast<float4*>(qn + (size_t)(m0 + row)*256 + n) = o;
        }
    }
}

// ---------------- self-attention over 100 keys, per (h, b, l) ----------------
__global__ void __launch_bounds__(128) k_sa(const float* __restrict__ qkv,
                                            float* __restrict__ osa){
    __shared__ __align__(16) float sK[100][32];
    __shared__ __align__(16) float sV[100][32];
    int h = blockIdx.x, b = blockIdx.y, l = blockIdx.z;
    int lb = l*4 + b;
    const float* qb = qkv + (size_t)lb*100*768;
    for (int idx = threadIdx.x; idx < 1600; idx += 128){
        int arr = (idx >= 800);
        int rem = arr ? idx - 800 : idx;
        int row = rem >> 3, qd = rem & 7;
        float4 v = *reinterpret_cast<const float4*>(
            qb + (size_t)row*768 + 256 + arr*256 + h*32 + qd*4);
        float* dstp = arr ? &sV[row][qd*4] : &sK[row][qd*4];
        *reinterpret_cast<float4*>(dstp) = v;
    }
    __syncthreads();
    int i = threadIdx.x;
    if (i < 100){
        float Q[32];
        const float4* qp4 = reinterpret_cast<const float4*>(qb + (size_t)i*768 + h*32);
#pragma unroll
        for (int qd = 0; qd < 8; qd++){
            float4 v = qp4[qd];
            Q[qd*4+0] = v.x; Q[qd*4+1] = v.y; Q[qd*4+2] = v.z; Q[qd*4+3] = v.w;
        }
        float m = -1e30f, s = 0.f, acc[32];
#pragma unroll
        for (int c = 0; c < 32; c++) acc[c] = 0.f;
        for (int j = 0; j < 100; j++){
            const float4* k4 = reinterpret_cast<const float4*>(sK[j]);
            float d = 0.f;
#pragma unroll
            for (int qd = 0; qd < 8; qd++){
                float4 kv = k4[qd];
                d = fmaf(Q[qd*4+0], kv.x, d); d = fmaf(Q[qd*4+1], kv.y, d);
                d = fmaf(Q[qd*4+2], kv.z, d); d = fmaf(Q[qd*4+3], kv.w, d);
            }
            d *= 0.17677669529663687f;
            const float4* v4 = reinterpret_cast<const float4*>(sV[j]);
            if (d > m){
                float f = __expf(m - d);
                m = d; s = fmaf(s, f, 1.f);
#pragma unroll
                for (int qd = 0; qd < 8; qd++){
                    float4 vv = v4[qd];
                    acc[qd*4+0] = fmaf(acc[qd*4+0], f, vv.x);
                    acc[qd*4+1] = fmaf(acc[qd*4+1], f, vv.y);
                    acc[qd*4+2] = fmaf(acc[qd*4+2], f, vv.z);
                    acc[qd*4+3] = fmaf(acc[qd*4+3], f, vv.w);
                }
            } else {
                float p = __expf(d - m);
                s += p;
#pragma unroll
                for (int qd = 0; qd < 8; qd++){
                    float4 vv = v4[qd];
                    acc[qd*4+0] = fmaf(p, vv.x, acc[qd*4+0]);
                    acc[qd*4+1] = fmaf(p, vv.y, acc[qd*4+1]);
                    acc[qd*4+2] = fmaf(p, vv.z, acc[qd*4+2]);
                    acc[qd*4+3] = fmaf(p, vv.w, acc[qd*4+3]);
                }
            }
        }
        float inv = 1.f / s;
        float* o = osa + (size_t)(lb*100 + i)*256 + h*32;
#pragma unroll
        for (int c = 0; c < 32; c++) o[c] = acc[c]*inv;
    }
}

// ---------------- cross-attention flash partials (cp.async pipelined) ----------------
__global__ void __launch_bounds__(128) k_cross(
    const float* __restrict__ qn, const float* __restrict__ Kg,
    const float* __restrict__ Vg, float* __restrict__ pm,
    float* __restrict__ ps, float* __restrict__ pacc)
{
    __shared__ __align__(16) float sKV[2][2][64][32];   // [buf][K/V][row][c]
    int ss = blockIdx.x, h = blockIdx.y, vb = blockIdx.z;
    int v = vb >> 2, b = vb & 3;
    int l = c_sl[ss];
    int Nl = c_N[l];
    int ck = c_ck[ss];
    int kbeg = c_sk[ss]*ck;
    int lb = l*4 + b;
    size_t kvbase = ((size_t)v*TOKV + c_off[l] + (size_t)b*Nl)*256 + h*32;
    const float* Kp = Kg + kvbase;
    const float* Vp = Vg + kvbase;
    int tid = threadIdx.x;
    uint32_t sbase = smem_u32(&sKV[0][0][0][0]);

    auto prefetch = [&](int kc, int buf){
        uint32_t stage = sbase + buf*16384;
#pragma unroll
        for (int it = 0; it < 8; it++){
            int idx = tid + it*128;
            int a = idx >> 9, rem = idx & 511;
            int row = rem >> 3, qd = rem & 7;
            const float* src = (a ? Vp : Kp) + (size_t)(kc + row)*256 + qd*4;
            cp16(stage + a*8192 + row*128 + qd*16, src);
        }
        cp_commit();
    };

    int i = tid;
    float Q[32];
    if (i < 100){
        const float4* qp4 = reinterpret_cast<const float4*>(
            qn + (size_t)(lb*100 + i)*256 + h*32);
#pragma unroll
        for (int qd = 0; qd < 8; qd++){
            float4 vq = qp4[qd];
            Q[qd*4+0] = vq.x; Q[qd*4+1] = vq.y; Q[qd*4+2] = vq.z; Q[qd*4+3] = vq.w;
        }
    }
    float m = -1e30f, s = 0.f, acc[32];
#pragma unroll
    for (int c = 0; c < 32; c++) acc[c] = 0.f;

    int nchunks = ck >> 6;
    prefetch(kbeg, 0);
    for (int cki = 0; cki < nchunks; cki++){
        int buf = cki & 1;
        if (cki + 1 < nchunks){ prefetch(kbeg + (cki+1)*64, buf ^ 1); cp_wait<1>(); }
        else                  { cp_wait<0>(); }
        __syncthreads();
        if (i < 100){
            for (int j = 0; j < 64; j++){
                const float4* k4 = reinterpret_cast<const float4*>(sKV[buf][0][j]);
                float d = 0.f;
#pragma unroll
                for (int qd = 0; qd < 8; qd++){
                    float4 kv = k4[qd];
                    d = fmaf(Q[qd*4+0], kv.x, d); d = fmaf(Q[qd*4+1], kv.y, d);
                    d = fmaf(Q[qd*4+2], kv.z, d); d = fmaf(Q[qd*4+3], kv.w, d);
                }
                d *= 0.17677669529663687f;
                const float4* v4 = reinterpret_cast<const float4*>(sKV[buf][1][j]);
                if (d > m){
                    float f = __expf(m - d);
                    m = d; s = fmaf(s, f, 1.f);
#pragma unroll
                    for (int qd = 0; qd < 8; qd++){
                        float4 vv = v4[qd];
                        acc[qd*4+0] = fmaf(acc[qd*4+0], f, vv.x);
                        acc[qd*4+1] = fmaf(acc[qd*4+1], f, vv.y);
                        acc[qd*4+2] = fmaf(acc[qd*4+2], f, vv.z);
                        acc[qd*4+3] = fmaf(acc[qd*4+3], f, vv.w);
                    }
                } else {
                    float p = __expf(d - m);
                    s += p;
#pragma unroll
                    for (int qd = 0; qd < 8; qd++){
                        float4 vv = v4[qd];
                        acc[qd*4+0] = fmaf(p, vv.x, acc[qd*4+0]);
                        acc[qd*4+1] = fmaf(p, vv.y, acc[qd*4+1]);
                        acc[qd*4+2] = fmaf(p, vv.z, acc[qd*4+2]);
                        acc[qd*4+3] = fmaf(p, vv.w, acc[qd*4+3]);
                    }
                }
            }
        }
        __syncthreads();
    }
    if (i < 100){
        int slot = (vb*8 + h)*22 + ss;
        pm[slot*100 + i] = m;
        ps[slot*100 + i] = s;
        float* pa = pacc + (size_t)(slot*100 + i)*32;
#pragma unroll
        for (int c = 0; c < 32; c++) pa[c] = acc[c];
    }
}

__global__ void __launch_bounds__(128) k_combine(
    const float* __restrict__ pm, const float* __restrict__ ps,
    const float* __restrict__ pacc, float* __restrict__ ocr)
{
    int l = blockIdx.x, h = blockIdx.y, vb = blockIdx.z;
    int i = threadIdx.x;
    if (i >= 100) return;
    int S = c_S[l], s0 = c_s0[l];
    int base = (vb*8 + h)*22 + s0;
    float M = -1e30f;
    for (int k = 0; k < S; k++) M = fmaxf(M, pm[(base + k)*100 + i]);
    float Ss = 0.f, acc[32];
#pragma unroll
    for (int c = 0; c < 32; c++) acc[c] = 0.f;
    for (int k = 0; k < S; k++){
        int slot = base + k;
        float f = __expf(pm[slot*100 + i] - M);
        Ss = fmaf(ps[slot*100 + i], f, Ss);
        const float* pa = pacc + (size_t)(slot*100 + i)*32;
#pragma unroll
        for (int c = 0; c < 32; c++) acc[c] = fmaf(pa[c], f, acc[c]);
    }
    float inv = 1.f / Ss;
    int v = vb >> 2, b = vb & 3;
    int lb = l*4 + b;
    float* o = ocr + (size_t)v*409600 + (size_t)(lb*100 + i)*256 + h*32;
#pragma unroll
    for (int c = 0; c < 32; c++) o[c] = acc[c]*inv;
}

// ---- matching score + both softmaxes, one block per lb ----
__global__ void __launch_bounds__(256) k_matchsm(const float* __restrict__ q12,
                                                 float* __restrict__ wr,
                                                 float* __restrict__ wc){
    extern __shared__ float buf[];          // >= 10100 floats
    float* sA = buf;                        // [100][33]
    float* sB = buf + 3300;                 // [100][33]
    int lb = blockIdx.x;
    int tid = threadIdx.x;
    int tx = tid & 15, ty = tid >> 4;
    const float* q1 = q12 + (size_t)lb*25600;
    const float* q2 = q12 + 409600 + (size_t)lb*25600;
    float acc[7][7];
#pragma unroll
    for (int a = 0; a < 7; a++)
#pragma unroll
        for (int bq = 0; bq < 7; bq++) acc[a][bq] = 0.f;
    for (int k0 = 0; k0 < 256; k0 += 32){
        __syncthreads();
        for (int idx = tid; idx < 3200; idx += 256){
            int r = idx >> 5, kk = idx & 31;
            sA[r*33 + kk] = q1[(size_t)r*256 + k0 + kk];
            sB[r*33 + kk] = q2[(size_t)r*256 + k0 + kk];
        }
        __syncthreads();
        for (int kk = 0; kk < 32; kk++){
            float a[7], b[7];
#pragma unroll
            for (int ii = 0; ii < 7; ii++){
                int i = ty + 16*ii;
                a[ii] = (i < 100) ? sA[i*33 + kk] : 0.f;
            }
#pragma unroll
            for (int jj = 0; jj < 7; jj++){
                int j = tx + 16*jj;
                b[jj] = (j < 100) ? sB[j*33 + kk] : 0.f;
            }
#pragma unroll
            for (int ii = 0; ii < 7; ii++)
#pragma unroll
                for (int jj = 0; jj < 7; jj++) acc[ii][jj] = fmaf(a[ii], b[jj], acc[ii][jj]);
        }
    }
    __syncthreads();                        // reuse buf as ms[100][101]
#pragma unroll
    for (int ii = 0; ii < 7; ii++){
        int i = ty + 16*ii;
        if (i < 100){
#pragma unroll
            for (int jj = 0; jj < 7; jj++){
                int j = tx + 16*jj;
                if (j < 100) buf[i*101 + j] = acc[ii][jj];
            }
        }
    }
    __syncthreads();
    int w = tid >> 5, lane = tid & 31;
    for (int r = w; r < 100; r += 8){
        float v0 = buf[r*101 + lane];
        float v1 = buf[r*101 + 32 + lane];
        float v2 = buf[r*101 + 64 + lane];
        float v3 = (lane < 4) ? buf[r*101 + 96 + lane] : -1e30f;
        float M = warpMax(fmaxf(fmaxf(v0, v1), fmaxf(v2, v3)));
        float p0 = __expf(v0 - M), p1 = __expf(v1 - M), p2 = __expf(v2 - M);
        float p3 = (lane < 4) ? __expf(v3 - M) : 0.f;
        float S = warpSum(p0 + p1 + p2 + p3);
        float inv = 1.f / S;
        float* o = wr + (size_t)lb*10000 + r*100;
        o[lane] = p0*inv; o[32 + lane] = p1*inv; o[64 + lane] = p2*inv;
        if (lane < 4) o[96 + lane] = p3*inv;
    }
    for (int cc = w; cc < 100; cc += 8){
        float v0 = buf[lane*101 + cc];
        float v1 = buf[(32 + lane)*101 + cc];
        float v2 = buf[(64 + lane)*101 + cc];
        float v3 = (lane < 4) ? buf[(96 + lane)*101 + cc] : -1e30f;
        float M = warpMax(fmaxf(fmaxf(v0, v1), fmaxf(v2, v3)));
        float p0 = __expf(v0 - M), p1 = __expf(v1 - M), p2 = __expf(v2 - M);
        float p3 = (lane < 4) ? __expf(v3 - M) : 0.f;
        float S = warpSum(p0 + p1 + p2 + p3);
        float inv = 1.f / S;
        float* o = wc + (size_t)lb*10000 + cc;
        o[lane*100] = p0*inv; o[(32 + lane)*100] = p1*inv; o[(64 + lane)*100] = p2*inv;
        if (lane < 4) o[(96 + lane)*100] = p3*inv;
    }
}

// -------- fuse (4 queries/block): t = qsa+q1+q2+Wr@q2+Wc^T@q1; softmax over c ----
__global__ void __launch_bounds__(256) k_fuse(
    const float* __restrict__ qsa, const float* __restrict__ q12,
    const float* __restrict__ wr, const float* __restrict__ wc,
    float* __restrict__ outp)
{
    __shared__ float swr[4][100];
    __shared__ float swc[4][100];
    __shared__ float sh[32];
    int i0 = blockIdx.x * 4, lb = blockIdx.y, c = threadIdx.x;
    const float* q1 = q12 + (size_t)lb*25600;
    const float* q2 = q12 + 409600 + (size_t)lb*25600;
    for (int idx = c; idx < 400; idx += 256){
        int ii = idx / 100, j = idx % 100;
        swr[ii][j] = wr[(size_t)lb*10000 + (i0+ii)*100 + j];
        swc[ii][j] = wc[(size_t)lb*10000 + j*100 + (i0+ii)];
    }
    __syncthreads();
    float acc[4];
#pragma unroll
    for (int ii = 0; ii < 4; ii++)
        acc[ii] = qsa[(size_t)(lb*100 + i0+ii)*256 + c]
                + q1[(size_t)(i0+ii)*256 + c] + q2[(size_t)(i0+ii)*256 + c];
    for (int j = 0; j < 100; j++){
        float q1v = q1[(size_t)j*256 + c];
        float q2v = q2[(size_t)j*256 + c];
#pragma unroll
        for (int ii = 0; ii < 4; ii++){
            acc[ii] = fmaf(swr[ii][j], q2v, acc[ii]);
            acc[ii] = fmaf(swc[ii][j], q1v, acc[ii]);
        }
    }
#pragma unroll
    for (int ii = 0; ii < 4; ii++){
        float M = blockMax(acc[ii], sh);
        float e = __expf(acc[ii] - M);
        float S = blockSum(e, sh);
        outp[(size_t)(lb*100 + i0+ii)*256 + c] = e / S;
    }
}

// ---------------- host ----------------
extern "C" void kernel_launch(void* const* d_in, const int* in_sizes, int n_in,
                              void* d_out, int out_size)
{
    float* arena;   cudaGetSymbolAddress((void**)&arena, g_buf);
    float* kvbuf;   cudaGetSymbolAddress((void**)&kvbuf, g_kv);
    __nv_bfloat16 *ahi, *alo, *whi, *wlo;
    cudaGetSymbolAddress((void**)&ahi, g_ahi);
    cudaGetSymbolAddress((void**)&alo, g_alo);
    cudaGetSymbolAddress((void**)&whi, g_whi);
    cudaGetSymbolAddress((void**)&wlo, g_wlo);
    float* bkv;     cudaGetSymbolAddress((void**)&bkv, g_bkv);

    float* q    = arena;                 // 409600
    float* qkv  = arena + 409600;        // 1228800
    float* osa  = arena + 1638400;       // 409600
    float* qsa  = arena + 2048000;       // 409600
    float* wqf  = arena + 2457600;       // 393216
    float* bqf  = arena + 2850816;       // 1536
    float* qn   = arena + 2867200;       // 409600
    float* ocr  = arena + 3276800;       // 819200
    float* q12  = arena + 4096000;       // 819200
    float* wr   = arena + 4915200;       // 160000
    float* wc   = arena + 5075200;       // 160000
    float* pm   = arena + 5235200;       // 140800
    float* ps   = arena + 5376000;       // 140800
    float* pacc = arena + 5516800;       // 4505600

    FeatPtrs fp;
    for (int i = 0; i < 8; i++) fp.p[i] = (const float*)d_in[i];
    const float* qe   = (const float*)d_in[8];
    const float* ng   = (const float*)d_in[9];
    const float* nb   = (const float*)d_in[10];
    const float* wq   = (const float*)d_in[11];
    const float* wk   = (const float*)d_in[12];
    const float* wv   = (const float*)d_in[13];
    const float* wp   = (const float*)d_in[14];
    const float* bp   = (const float*)d_in[15];
    const float* wqkv = (const float*)d_in[16];
    const float* swp  = (const float*)d_in[17];
    const float* sbp  = (const float*)d_in[18];

    cudaFuncSetAttribute(k_kvgemm, cudaFuncAttributeMaxDynamicSharedMemorySize, 131072);

    k_init_q<<<1600, 256>>>(qe, q);
    k_tok_ln<<<dim3(680, 2), 256>>>(fp, ahi, alo);
    k_prep_w<<<12, 256>>>(wk, wv, ng, nb, whi, wlo, bkv);
    k_gemm64<<<dim3(25, 6), 256>>>(q, wqkv, nullptr, qkv, 1600, 768);   // d=0, profiled slot
    k_kvgemm<<<dim3(340, 2, 12), 512, 131072>>>(ahi, alo, whi, wlo, bkv, kvbuf);
    k_prep_wq<<<6, 256>>>(wq, ng, nb, wqf, bqf);

    for (int d = 0; d < 6; d++){
        if (d > 0)
            k_gemm64<<<dim3(25, 6), 256>>>(q, wqkv + (size_t)d*256*768,
                                           nullptr, qkv, 1600, 768);
        k_sa<<<dim3(8, 4, 4), 128>>>(qkv, osa);
        k_sa2<<<50, 256>>>(osa, swp + (size_t)d*65536, sbp + d*256,
                           wqf + (size_t)d*65536, bqf + d*256, qsa, qn);
        k_cross<<<dim3(22, 8, 8), 128>>>(qn, kvbuf + (size_t)(2*d)*KVSZ,
                                         kvbuf + (size_t)(2*d+1)*KVSZ, pm, ps, pacc);
        k_combine<<<dim3(4, 8, 8), 128>>>(pm, ps, pacc, ocr);
        k_gemm64<<<dim3(50, 2), 256>>>(ocr, wp + (size_t)d*65536,
                                       bp + d*256, q12, 3200, 256);
        k_matchsm<<<16, 256, 10100*sizeof(float)>>>(q12, wr, wc);
        k_fuse<<<dim3(25, 16), 256>>>(qsa, q12, wr, wc,
                                      (d == 5) ? (float*)d_out : q);
    }
}

// round 11
// speedup vs baseline: 1.4984x; 1.0219x over previous
#include <cuda_runtime.h>
#include <cuda_bf16.h>
#include <cstdint>
#include <math.h>

#define TOKV 21760            // per-view feature tokens: 4*(4096+1024+256+64)
#define AROWS 43520           // 2 views
#define KVSZ  11141120        // 43520*256
#define MPAD  1664            // 1600 padded to 13*128

__constant__ int c_N[4]   = {4096, 1024, 256, 64};
__constant__ int c_off[4] = {0, 16384, 20480, 21504};
// 22 cross-attn split slots (256-key chunks; level 3 has 64)
__constant__ int c_sl[22] = {0,0,0,0,0,0,0,0,0,0,0,0,0,0,0,0, 1,1,1,1, 2, 3};
__constant__ int c_sk[22] = {0,1,2,3,4,5,6,7,8,9,10,11,12,13,14,15, 0,1,2,3, 0, 0};
__constant__ int c_ck[22] = {256,256,256,256,256,256,256,256,256,256,256,256,256,256,256,256,
                             256,256,256,256, 256, 64};
__constant__ int c_S[4]  = {16,4,1,1};
__constant__ int c_s0[4] = {0,16,20,21};

// ---- device scratch (allocations forbidden) ----
__device__ float g_kv[12*KVSZ];                  // K/V for all 6 depths (535 MB)
__device__ __nv_bfloat16 g_ahi[AROWS*256];
__device__ __nv_bfloat16 g_alo[AROWS*256];
__device__ __nv_bfloat16 g_whi[12*256*256];
__device__ __nv_bfloat16 g_wlo[12*256*256];
__device__ float g_bkv[12*256];
// per-depth GEMM operands (bf16 hi/lo)
__device__ __nv_bfloat16 g_qh[MPAD*256],  g_ql[MPAD*256];
__device__ __nv_bfloat16 g_oh[MPAD*256],  g_ol[MPAD*256];
__device__ __nv_bfloat16 g_xh[MPAD*256],  g_xl[MPAD*256];
__device__ __nv_bfloat16 g_och[3200*256], g_ocl[3200*256];
__device__ __nv_bfloat16 g_wqkvh[6*768*256], g_wqkvl[6*768*256];
__device__ __nv_bfloat16 g_wswh[6*256*256],  g_wswl[6*256*256];
__device__ __nv_bfloat16 g_wqh[6*256*256],   g_wql[6*256*256];
__device__ __nv_bfloat16 g_wph[6*256*256],   g_wpl[6*256*256];
__device__ float g_bsw[1536], g_bwq[1536], g_bwp[1536];
__device__ float g_buf[9000000];

struct FeatPtrs { const float* p[8]; };

// ---------------- PTX helpers ----------------
__device__ __forceinline__ uint32_t smem_u32(const void* p){
    uint32_t a;
    asm("{ .reg .u64 t; cvta.to.shared.u64 t, %1; cvt.u32.u64 %0, t; }" : "=r"(a) : "l"(p));
    return a;
}
__device__ __forceinline__ void cp16(uint32_t s, const void* g){
    asm volatile("cp.async.cg.shared.global [%0], [%1], 16;" :: "r"(s), "l"(g) : "memory");
}
__device__ __forceinline__ void cp_commit(){
    asm volatile("cp.async.commit_group;" ::: "memory");
}
template<int N>
__device__ __forceinline__ void cp_wait(){
    asm volatile("cp.async.wait_group %0;" :: "n"(N) : "memory");
}
__device__ __forceinline__ void ldsm4(uint32_t* r, uint32_t a){
    asm volatile("ldmatrix.sync.aligned.m8n8.x4.shared.b16 {%0,%1,%2,%3}, [%4];"
                 : "=r"(r[0]), "=r"(r[1]), "=r"(r[2]), "=r"(r[3]) : "r"(a));
}
__device__ __forceinline__ void mma16816(float* c, const uint32_t* a,
                                         uint32_t b0, uint32_t b1){
    asm volatile(
        "mma.sync.aligned.m16n8k16.row.col.f32.bf16.bf16.f32 "
        "{%0,%1,%2,%3}, {%4,%5,%6,%7}, {%8,%9}, {%0,%1,%2,%3};"
        : "+f"(c[0]), "+f"(c[1]), "+f"(c[2]), "+f"(c[3])
        : "r"(a[0]), "r"(a[1]), "r"(a[2]), "r"(a[3]), "r"(b0), "r"(b1));
}
__device__ __forceinline__ void hilo(float v, __nv_bfloat16* ph, __nv_bfloat16* pl){
    __nv_bfloat16 h = __float2bfloat16(v);
    *ph = h;
    *pl = __float2bfloat16(v - __bfloat162float(h));
}

// ---------------- reductions ----------------
__device__ __forceinline__ float warpSum(float v){
#pragma unroll
    for (int o = 16; o > 0; o >>= 1) v += __shfl_xor_sync(0xffffffffu, v, o);
    return v;
}
__device__ __forceinline__ float warpMax(float v){
#pragma unroll
    for (int o = 16; o > 0; o >>= 1) v = fmaxf(v, __shfl_xor_sync(0xffffffffu, v, o));
    return v;
}
__device__ __forceinline__ float blockSum(float v, float* sh){
    int lane = threadIdx.x & 31, w = threadIdx.x >> 5;
    int nw = blockDim.x >> 5;
    __syncthreads();
    v = warpSum(v);
    if (lane == 0) sh[w] = v;
    __syncthreads();
    if (w == 0){
        float r = (threadIdx.x < nw) ? sh[threadIdx.x] : 0.f;
        r = warpSum(r);
        if (lane == 0) sh[0] = r;
    }
    __syncthreads();
    return sh[0];
}
__device__ __forceinline__ float blockMax(float v, float* sh){
    int lane = threadIdx.x & 31, w = threadIdx.x >> 5;
    int nw = blockDim.x >> 5;
    __syncthreads();
    v = warpMax(v);
    if (lane == 0) sh[w] = v;
    __syncthreads();
    if (w == 0){
        float r = (threadIdx.x < nw) ? sh[threadIdx.x] : -1e30f;
        r = warpMax(r);
        if (lane == 0) sh[0] = r;
    }
    __syncthreads();
    return sh[0];
}

// ---- tokenize + LN normalization -> bf16 hi/lo (coalesced; affine folded into W) ----
__global__ void __launch_bounds__(256) k_tok_ln(FeatPtrs fp,
    __nv_bfloat16* __restrict__ ahi, __nv_bfloat16* __restrict__ alo)
{
    __shared__ float s[256][33];
    __shared__ float ps[8][32], pq[8][32];
    __shared__ float mean[32], rinv[32];
    int r = blockIdx.x, v = blockIdx.y;
    int l = (r < 512) ? 0 : (r < 640) ? 1 : (r < 672) ? 2 : 3;
    int off32 = (l == 0) ? 0 : (l == 1) ? 512 : (l == 2) ? 640 : 672;
    int Nl = c_N[l];
    int idx = r - off32;
    int tpb = Nl >> 5;
    int b = idx / tpb, t0 = (idx % tpb) * 32;
    const float* f = fp.p[v*4 + l];
    int g = threadIdx.x >> 5, t = threadIdx.x & 31;
    for (int cc = g; cc < 256; cc += 8)
        s[cc][t] = f[((size_t)(b*256 + cc))*Nl + t0 + t];
    __syncthreads();
    float sx = 0.f, sq = 0.f;
#pragma unroll
    for (int k = 0; k < 32; k++){
        float x = s[g*32 + k][t];
        sx += x; sq = fmaf(x, x, sq);
    }
    ps[g][t] = sx; pq[g][t] = sq;
    __syncthreads();
    if (threadIdx.x < 32){
        float m = 0.f, qq = 0.f;
#pragma unroll
        for (int gg = 0; gg < 8; gg++){ m += ps[gg][threadIdx.x]; qq += pq[gg][threadIdx.x]; }
        m *= (1.f/256.f);
        float var = qq*(1.f/256.f) - m*m;
        mean[threadIdx.x] = m;
        rinv[threadIdx.x] = rsqrtf(var + 1e-5f);
    }
    __syncthreads();
    int c = threadIdx.x;
    size_t rowbase = (size_t)v*TOKV + c_off[l] + (size_t)b*Nl + t0;
    for (int tt = 0; tt < 32; tt++){
        float val = (s[c][tt] - mean[tt]) * rinv[tt];
        hilo(val, &ahi[(rowbase + tt)*256 + c], &alo[(rowbase + tt)*256 + c]);
    }
}

// ---- prep KV weights: Wt[n][k] = g[k]*W[k][n] bf16 hi/lo; bias'[n] = b@W ----
__global__ void __launch_bounds__(256) k_prep_w(
    const float* __restrict__ wk, const float* __restrict__ wv,
    const float* __restrict__ ng, const float* __restrict__ nb,
    __nv_bfloat16* __restrict__ whi, __nv_bfloat16* __restrict__ wlo,
    float* __restrict__ bkv)
{
    int s = blockIdx.x, n = threadIdx.x;
    int d = s >> 1;
    const float* W = ((s & 1) ? wv : wk) + (size_t)d*65536;
    const float* g = ng + d*256;
    const float* b = nb + d*256;
    float bias = 0.f;
    size_t obase = ((size_t)s*256 + n)*256;
    for (int k = 0; k < 256; k++){
        float w0 = W[k*256 + n];
        bias = fmaf(b[k], w0, bias);
        float w = g[k]*w0;
        hilo(w, &whi[obase + k], &wlo[obase + k]);
    }
    bkv[s*256 + n] = bias;
}

// ---- generic weight prep: Wt[n][k] hi/lo (+optional g fold, bias fold, add bias) ----
__global__ void __launch_bounds__(256) k_prep_wt(
    const float* __restrict__ W, const float* __restrict__ g,
    const float* __restrict__ bf, const float* __restrict__ ab,
    __nv_bfloat16* __restrict__ wh, __nv_bfloat16* __restrict__ wl,
    float* __restrict__ bo, int N)
{
    int d = blockIdx.y;
    int n = blockIdx.x*256 + threadIdx.x;
    const float* Wd = W + (size_t)d*256*N;
    float bias = ab ? ab[(size_t)d*N + n] : 0.f;
    size_t ob = ((size_t)d*N + n)*256;
    for (int k = 0; k < 256; k++){
        float w0 = Wd[(size_t)k*N + n];
        if (bf) bias = fmaf(bf[d*256 + k], w0, bias);
        float w = g ? g[d*256 + k]*w0 : w0;
        hilo(w, &wh[ob + k], &wl[ob + k]);
    }
    if (bo) bo[(size_t)d*N + n] = bias;
}

__global__ void k_init_q(const float* __restrict__ qe,
                         __nv_bfloat16* __restrict__ qh,
                         __nv_bfloat16* __restrict__ ql){
    int row = blockIdx.x, c = threadIdx.x;
    float val = qe[(row % 100)*256 + c];
    hilo(val, &qh[(size_t)row*256 + c], &ql[(size_t)row*256 + c]);
}

// ---- mma.sync KV GEMM, 512 threads: C[slot][43520,256] = A(hi/lo)@Wt(hi/lo)^T + bias
__global__ void __launch_bounds__(512) k_kvgemm(
    const __nv_bfloat16* __restrict__ Ahi, const __nv_bfloat16* __restrict__ Alo,
    const __nv_bfloat16* __restrict__ Whi, const __nv_bfloat16* __restrict__ Wlo,
    const float* __restrict__ bkv, float* __restrict__ Cbuf)
{
    extern __shared__ char sm[];
    uint32_t sb = smem_u32(sm);
    int tid = threadIdx.x, lane = tid & 31, warp = tid >> 5;
    int mt = blockIdx.x, nh = blockIdx.y, slot = blockIdx.z;
    size_t arow0 = (size_t)mt * 128;
    const __nv_bfloat16* wh = Whi + (size_t)slot*65536 + (size_t)nh*128*256;
    const __nv_bfloat16* wl = Wlo + (size_t)slot*65536 + (size_t)nh*128*256;

    int wm = warp >> 2, wn = warp & 3;           // warp tile: 32m x 32n

    float acc[2][4][4];
#pragma unroll
    for (int mi = 0; mi < 2; mi++)
#pragma unroll
        for (int ni = 0; ni < 4; ni++)
#pragma unroll
            for (int k = 0; k < 4; k++) acc[mi][ni][k] = 0.f;

    auto prefetch = [&](int ck, int buf){
        uint32_t stage = sb + buf*65536;
#pragma unroll
        for (int it = 0; it < 2; it++){
            int i = tid + it*512;
            int row = i >> 3, g = i & 7;
            uint32_t so = stage + row*128 + (((g ^ (row & 7)) << 4));
            cp16(so,         Ahi + (arow0 + row)*256 + ck*64 + g*8);
            cp16(so + 16384, Alo + (arow0 + row)*256 + ck*64 + g*8);
            cp16(so + 32768, wh + row*256 + ck*64 + g*8);
            cp16(so + 49152, wl + row*256 + ck*64 + g*8);
        }
        cp_commit();
    };

    prefetch(0, 0);

    for (int ck = 0; ck < 4; ck++){
        int buf = ck & 1;
        if (ck + 1 < 4){ prefetch(ck + 1, (ck + 1) & 1); cp_wait<1>(); }
        else           { cp_wait<0>(); }
        __syncthreads();

        uint32_t stage = sb + buf*65536;
#pragma unroll
        for (int k16 = 0; k16 < 4; k16++){
            int msel = lane >> 3;
            int rsub = (msel & 1)*8 + (lane & 7);
            int gg   = k16*2 + (msel >> 1);
            uint32_t ah[2][4], al[2][4];
#pragma unroll
            for (int mi = 0; mi < 2; mi++){
                int r = wm*32 + mi*16 + rsub;
                uint32_t ad = stage + r*128 + (((gg ^ (r & 7)) << 4));
                ldsm4(ah[mi], ad);
                ldsm4(al[mi], ad + 16384);
            }
            uint32_t bh[2][4], bl[2][4];
#pragma unroll
            for (int nj = 0; nj < 2; nj++){
                int r = wn*32 + nj*16 + rsub;
                uint32_t ad = stage + 32768 + r*128 + (((gg ^ (r & 7)) << 4));
                ldsm4(bh[nj], ad);
                ldsm4(bl[nj], ad + 16384);
            }
#pragma unroll
            for (int mi = 0; mi < 2; mi++)
#pragma unroll
                for (int ni = 0; ni < 4; ni++){
                    int nj = ni >> 1, sel = ni & 1;
                    mma16816(acc[mi][ni], ah[mi], bh[nj][sel], bh[nj][2+sel]);
                    mma16816(acc[mi][ni], ah[mi], bl[nj][sel], bl[nj][2+sel]);
                    mma16816(acc[mi][ni], al[mi], bh[nj][sel], bh[nj][2+sel]);
                }
        }
        __syncthreads();
    }

    // epilogue: stage fp32 tile in smem (stride 132), stream out coalesced
    float* st = reinterpret_cast<float*>(sm);
#pragma unroll
    for (int mi = 0; mi < 2; mi++)
#pragma unroll
        for (int ni = 0; ni < 4; ni++){
            int r0 = wm*32 + mi*16 + (lane >> 2);
            int c0 = wn*32 + ni*8 + (lane & 3)*2;
            *reinterpret_cast<float2*>(st + r0*132 + c0)       = make_float2(acc[mi][ni][0], acc[mi][ni][1]);
            *reinterpret_cast<float2*>(st + (r0 + 8)*132 + c0) = make_float2(acc[mi][ni][2], acc[mi][ni][3]);
        }
    __syncthreads();
    const float4* bp4 = reinterpret_cast<const float4*>(bkv + slot*256 + nh*128);
    float* dst = Cbuf + (size_t)slot*KVSZ + arow0*256 + nh*128;
#pragma unroll
    for (int it = 0; it < 8; it++){
        int i = tid + it*512;
        int row = i >> 5, q = i & 31;
        float4 v = *reinterpret_cast<float4*>(st + row*132 + q*4);
        float4 bb = bp4[q];
        v.x += bb.x; v.y += bb.y; v.z += bb.z; v.w += bb.w;
        *reinterpret_cast<float4*>(dst + (size_t)row*256 + q*4) = v;
    }
}

// ---- mma.sync small GEMM: C[.,N] = A(hi/lo)[.,256] @ Wt(hi/lo)^T (+bias) ----
// grid (mtiles, N/128), 256 threads, tile 128x128 (R8-proven core).
__global__ void __launch_bounds__(256) k_qgemm(
    const __nv_bfloat16* __restrict__ Ah, const __nv_bfloat16* __restrict__ Al,
    const __nv_bfloat16* __restrict__ Wh, const __nv_bfloat16* __restrict__ Wl,
    const float* __restrict__ bias, float* __restrict__ C, int ldc)
{
    extern __shared__ char sm[];
    uint32_t sb = smem_u32(sm);
    int tid = threadIdx.x, lane = tid & 31, warp = tid >> 5;
    int mt = blockIdx.x, nt = blockIdx.y;
    size_t arow0 = (size_t)mt * 128;
    const __nv_bfloat16* wh = Wh + (size_t)nt*128*256;
    const __nv_bfloat16* wl = Wl + (size_t)nt*128*256;

    int wm = warp >> 1, wn = warp & 1;           // warp tile: 32m x 64n

    float acc[2][8][4];
#pragma unroll
    for (int mi = 0; mi < 2; mi++)
#pragma unroll
        for (int ni = 0; ni < 8; ni++)
#pragma unroll
            for (int k = 0; k < 4; k++) acc[mi][ni][k] = 0.f;

    auto prefetch = [&](int ck, int buf){
        uint32_t stage = sb + buf*65536;
#pragma unroll
        for (int it = 0; it < 4; it++){
            int i = tid + it*256;
            int row = i >> 3, g = i & 7;
            uint32_t so = stage + row*128 + (((g ^ (row & 7)) << 4));
            cp16(so,         Ah + (arow0 + row)*256 + ck*64 + g*8);
            cp16(so + 16384, Al + (arow0 + row)*256 + ck*64 + g*8);
            cp16(so + 32768, wh + row*256 + ck*64 + g*8);
            cp16(so + 49152, wl + row*256 + ck*64 + g*8);
        }
        cp_commit();
    };

    prefetch(0, 0);

    for (int ck = 0; ck < 4; ck++){
        int buf = ck & 1;
        if (ck + 1 < 4){ prefetch(ck + 1, (ck + 1) & 1); cp_wait<1>(); }
        else           { cp_wait<0>(); }
        __syncthreads();

        uint32_t stage = sb + buf*65536;
#pragma unroll
        for (int k16 = 0; k16 < 4; k16++){
            int msel = lane >> 3;
            int rsub = (msel & 1)*8 + (lane & 7);
            int gg   = k16*2 + (msel >> 1);
            uint32_t ah[2][4], al[2][4];
#pragma unroll
            for (int mi = 0; mi < 2; mi++){
                int r = wm*32 + mi*16 + rsub;
                uint32_t ad = stage + r*128 + (((gg ^ (r & 7)) << 4));
                ldsm4(ah[mi], ad);
                ldsm4(al[mi], ad + 16384);
            }
            uint32_t bh[4][4], bl[4][4];
#pragma unroll
            for (int nj = 0; nj < 4; nj++){
                int r = wn*64 + nj*16 + rsub;
                uint32_t ad = stage + 32768 + r*128 + (((gg ^ (r & 7)) << 4));
                ldsm4(bh[nj], ad);
                ldsm4(bl[nj], ad + 16384);
            }
#pragma unroll
            for (int mi = 0; mi < 2; mi++)
#pragma unroll
                for (int ni = 0; ni < 8; ni++){
                    int nj = ni >> 1, sel = ni & 1;
                    mma16816(acc[mi][ni], ah[mi], bh[nj][sel], bh[nj][2+sel]);
                    mma16816(acc[mi][ni], ah[mi], bl[nj][sel], bl[nj][2+sel]);
                    mma16816(acc[mi][ni], al[mi], bh[nj][sel], bh[nj][2+sel]);
                }
        }
        __syncthreads();
    }

    int n0 = nt*128;
#pragma unroll
    for (int mi = 0; mi < 2; mi++){
#pragma unroll
        for (int ni = 0; ni < 8; ni++){
            int row = (int)arow0 + wm*32 + mi*16 + (lane >> 2);
            int col = n0 + wn*64 + ni*8 + (lane & 3)*2;
            float bx = bias ? bias[col]     : 0.f;
            float by = bias ? bias[col + 1] : 0.f;
            float2 v0 = make_float2(acc[mi][ni][0] + bx, acc[mi][ni][1] + by);
            float2 v1 = make_float2(acc[mi][ni][2] + bx, acc[mi][ni][3] + by);
            *reinterpret_cast<float2*>(C + (size_t)row*ldc + col) = v0;
            *reinterpret_cast<float2*>(C + (size_t)(row + 8)*ldc + col) = v1;
        }
    }
}

// ---- LN rows of qsa -> bf16 hi/lo ----
__global__ void __launch_bounds__(256) k_lnsplit(const float* __restrict__ in,
    __nv_bfloat16* __restrict__ xh, __nv_bfloat16* __restrict__ xl)
{
    __shared__ float sh[32];
    int row = blockIdx.x, c = threadIdx.x;
    float x = in[(size_t)row*256 + c];
    float m = blockSum(x, sh) * (1.f/256.f);
    float d = x - m;
    float var = blockSum(d*d, sh) * (1.f/256.f);
    float v = d * rsqrtf(var + 1e-5f);
    hilo(v, &xh[(size_t)row*256 + c], &xl[(size_t)row*256 + c]);
}

// ---------------- self-attention over 100 keys, per (h, b, l) ----------------
__global__ void __launch_bounds__(128) k_sa(const float* __restrict__ qkv,
                                            __nv_bfloat16* __restrict__ oh,
                                            __nv_bfloat16* __restrict__ ol){
    __shared__ __align__(16) float sK[100][32];
    __shared__ __align__(16) float sV[100][32];
    int h = blockIdx.x, b = blockIdx.y, l = blockIdx.z;
    int lb = l*4 + b;
    const float* qb = qkv + (size_t)lb*100*768;
    for (int idx = threadIdx.x; idx < 1600; idx += 128){
        int arr = (idx >= 800);
        int rem = arr ? idx - 800 : idx;
        int row = rem >> 3, qd = rem & 7;
        float4 v = *reinterpret_cast<const float4*>(
            qb + (size_t)row*768 + 256 + arr*256 + h*32 + qd*4);
        float* dstp = arr ? &sV[row][qd*4] : &sK[row][qd*4];
        *reinterpret_cast<float4*>(dstp) = v;
    }
    __syncthreads();
    int i = threadIdx.x;
    if (i < 100){
        float Q[32];
        const float4* qp4 = reinterpret_cast<const float4*>(qb + (size_t)i*768 + h*32);
#pragma unroll
        for (int qd = 0; qd < 8; qd++){
            float4 v = qp4[qd];
            Q[qd*4+0] = v.x; Q[qd*4+1] = v.y; Q[qd*4+2] = v.z; Q[qd*4+3] = v.w;
        }
        float m = -1e30f, s = 0.f, acc[32];
#pragma unroll
        for (int c = 0; c < 32; c++) acc[c] = 0.f;
        for (int j = 0; j < 100; j++){
            const float4* k4 = reinterpret_cast<const float4*>(sK[j]);
            float d = 0.f;
#pragma unroll
            for (int qd = 0; qd < 8; qd++){
                float4 kv = k4[qd];
                d = fmaf(Q[qd*4+0], kv.x, d); d = fmaf(Q[qd*4+1], kv.y, d);
                d = fmaf(Q[qd*4+2], kv.z, d); d = fmaf(Q[qd*4+3], kv.w, d);
            }
            d *= 0.17677669529663687f;
            const float4* v4 = reinterpret_cast<const float4*>(sV[j]);
            if (d > m){
                float f = __expf(m - d);
                m = d; s = fmaf(s, f, 1.f);
#pragma unroll
                for (int qd = 0; qd < 8; qd++){
                    float4 vv = v4[qd];
                    acc[qd*4+0] = fmaf(acc[qd*4+0], f, vv.x);
                    acc[qd*4+1] = fmaf(acc[qd*4+1], f, vv.y);
                    acc[qd*4+2] = fmaf(acc[qd*4+2], f, vv.z);
                    acc[qd*4+3] = fmaf(acc[qd*4+3], f, vv.w);
                }
            } else {
                float p = __expf(d - m);
                s += p;
#pragma unroll
                for (int qd = 0; qd < 8; qd++){
                    float4 vv = v4[qd];
                    acc[qd*4+0] = fmaf(p, vv.x, acc[qd*4+0]);
                    acc[qd*4+1] = fmaf(p, vv.y, acc[qd*4+1]);
                    acc[qd*4+2] = fmaf(p, vv.z, acc[qd*4+2]);
                    acc[qd*4+3] = fmaf(p, vv.w, acc[qd*4+3]);
                }
            }
        }
        float inv = 1.f / s;
        size_t ob = (size_t)(lb*100 + i)*256 + h*32;
#pragma unroll
        for (int c = 0; c < 32; c++)
            hilo(acc[c]*inv, &oh[ob + c], &ol[ob + c]);
    }
}

// ---------------- cross-attention flash partials (cp.async pipelined) ----------------
__global__ void __launch_bounds__(128) k_cross(
    const float* __restrict__ qn, const float* __restrict__ Kg,
    const float* __restrict__ Vg, float* __restrict__ pm,
    float* __restrict__ ps, float* __restrict__ pacc)
{
    __shared__ __align__(16) float sKV[2][2][64][32];   // [buf][K/V][row][c]
    int ss = blockIdx.x, h = blockIdx.y, vb = blockIdx.z;
    int v = vb >> 2, b = vb & 3;
    int l = c_sl[ss];
    int Nl = c_N[l];
    int ck = c_ck[ss];
    int kbeg = c_sk[ss]*ck;
    int lb = l*4 + b;
    size_t kvbase = ((size_t)v*TOKV + c_off[l] + (size_t)b*Nl)*256 + h*32;
    const float* Kp = Kg + kvbase;
    const float* Vp = Vg + kvbase;
    int tid = threadIdx.x;
    uint32_t sbase = smem_u32(&sKV[0][0][0][0]);

    auto prefetch = [&](int kc, int buf){
        uint32_t stage = sbase + buf*16384;
#pragma unroll
        for (int it = 0; it < 8; it++){
            int idx = tid + it*128;
            int a = idx >> 9, rem = idx & 511;
            int row = rem >> 3, qd = rem & 7;
            const float* src = (a ? Vp : Kp) + (size_t)(kc + row)*256 + qd*4;
            cp16(stage + a*8192 + row*128 + qd*16, src);
        }
        cp_commit();
    };

    int i = tid;
    float Q[32];
    if (i < 100){
        const float4* qp4 = reinterpret_cast<const float4*>(
            qn + (size_t)(lb*100 + i)*256 + h*32);
#pragma unroll
        for (int qd = 0; qd < 8; qd++){
            float4 vq = qp4[qd];
            Q[qd*4+0] = vq.x; Q[qd*4+1] = vq.y; Q[qd*4+2] = vq.z; Q[qd*4+3] = vq.w;
        }
    }
    float m = -1e30f, s = 0.f, acc[32];
#pragma unroll
    for (int c = 0; c < 32; c++) acc[c] = 0.f;

    int nchunks = ck >> 6;
    prefetch(kbeg, 0);
    for (int cki = 0; cki < nchunks; cki++){
        int buf = cki & 1;
        if (cki + 1 < nchunks){ prefetch(kbeg + (cki+1)*64, buf ^ 1); cp_wait<1>(); }
        else                  { cp_wait<0>(); }
        __syncthreads();
        if (i < 100){
            for (int j = 0; j < 64; j++){
                const float4* k4 = reinterpret_cast<const float4*>(sKV[buf][0][j]);
                float d = 0.f;
#pragma unroll
                for (int qd = 0; qd < 8; qd++){
                    float4 kv = k4[qd];
                    d = fmaf(Q[qd*4+0], kv.x, d); d = fmaf(Q[qd*4+1], kv.y, d);
                    d = fmaf(Q[qd*4+2], kv.z, d); d = fmaf(Q[qd*4+3], kv.w, d);
                }
                d *= 0.17677669529663687f;
                const float4* v4 = reinterpret_cast<const float4*>(sKV[buf][1][j]);
                if (d > m){
                    float f = __expf(m - d);
                    m = d; s = fmaf(s, f, 1.f);
#pragma unroll
                    for (int qd = 0; qd < 8; qd++){
                        float4 vv = v4[qd];
                        acc[qd*4+0] = fmaf(acc[qd*4+0], f, vv.x);
                        acc[qd*4+1] = fmaf(acc[qd*4+1], f, vv.y);
                        acc[qd*4+2] = fmaf(acc[qd*4+2], f, vv.z);
                        acc[qd*4+3] = fmaf(acc[qd*4+3], f, vv.w);
                    }
                } else {
                    float p = __expf(d - m);
                    s += p;
#pragma unroll
                    for (int qd = 0; qd < 8; qd++){
                        float4 vv = v4[qd];
                        acc[qd*4+0] = fmaf(p, vv.x, acc[qd*4+0]);
                        acc[qd*4+1] = fmaf(p, vv.y, acc[qd*4+1]);
                        acc[qd*4+2] = fmaf(p, vv.z, acc[qd*4+2]);
                        acc[qd*4+3] = fmaf(p, vv.w, acc[qd*4+3]);
                    }
                }
            }
        }
        __syncthreads();
    }
    if (i < 100){
        int slot = (vb*8 + h)*22 + ss;
        pm[slot*100 + i] = m;
        ps[slot*100 + i] = s;
        float* pa = pacc + (size_t)(slot*100 + i)*32;
#pragma unroll
        for (int c = 0; c < 32; c++) pa[c] = acc[c];
    }
}

__global__ void __launch_bounds__(128) k_combine(
    const float* __restrict__ pm, const float* __restrict__ ps,
    const float* __restrict__ pacc,
    __nv_bfloat16* __restrict__ och, __nv_bfloat16* __restrict__ ocl)
{
    int l = blockIdx.x, h = blockIdx.y, vb = blockIdx.z;
    int i = threadIdx.x;
    if (i >= 100) return;
    int S = c_S[l], s0 = c_s0[l];
    int base = (vb*8 + h)*22 + s0;
    float M = -1e30f;
    for (int k = 0; k < S; k++) M = fmaxf(M, pm[(base + k)*100 + i]);
    float Ss = 0.f, acc[32];
#pragma unroll
    for (int c = 0; c < 32; c++) acc[c] = 0.f;
    for (int k = 0; k < S; k++){
        int slot = base + k;
        float f = __expf(pm[slot*100 + i] - M);
        Ss = fmaf(ps[slot*100 + i], f, Ss);
        const float* pa = pacc + (size_t)(slot*100 + i)*32;
#pragma unroll
        for (int c = 0; c < 32; c++) acc[c] = fmaf(pa[c], f, acc[c]);
    }
    float inv = 1.f / Ss;
    int v = vb >> 2, b = vb & 3;
    int lb = l*4 + b;
    size_t ob = (size_t)(v*1600 + lb*100 + i)*256 + h*32;
#pragma unroll
    for (int c = 0; c < 32; c++)
        hilo(acc[c]*inv, &och[ob + c], &ocl[ob + c]);
}

// ---- matching score + both softmaxes, one block per lb ----
__global__ void __launch_bounds__(256) k_matchsm(const float* __restrict__ q12,
                                                 float* __restrict__ wr,
                                                 float* __restrict__ wc){
    extern __shared__ float buf[];          // >= 10100 floats
    float* sA = buf;                        // [100][33]
    float* sB = buf + 3300;                 // [100][33]
    int lb = blockIdx.x;
    int tid = threadIdx.x;
    int tx = tid & 15, ty = tid >> 4;
    const float* q1 = q12 + (size_t)lb*25600;
    const float* q2 = q12 + 409600 + (size_t)lb*25600;
    float acc[7][7];
#pragma unroll
    for (int a = 0; a < 7; a++)
#pragma unroll
        for (int bq = 0; bq < 7; bq++) acc[a][bq] = 0.f;
    for (int k0 = 0; k0 < 256; k0 += 32){
        __syncthreads();
        for (int idx = tid; idx < 3200; idx += 256){
            int r = idx >> 5, kk = idx & 31;
            sA[r*33 + kk] = q1[(size_t)r*256 + k0 + kk];
            sB[r*33 + kk] = q2[(size_t)r*256 + k0 + kk];
        }
        __syncthreads();
        for (int kk = 0; kk < 32; kk++){
            float a[7], b[7];
#pragma unroll
            for (int ii = 0; ii < 7; ii++){
                int i = ty + 16*ii;
                a[ii] = (i < 100) ? sA[i*33 + kk] : 0.f;
            }
#pragma unroll
            for (int jj = 0; jj < 7; jj++){
                int j = tx + 16*jj;
                b[jj] = (j < 100) ? sB[j*33 + kk] : 0.f;
            }
#pragma unroll
            for (int ii = 0; ii < 7; ii++)
#pragma unroll
                for (int jj = 0; jj < 7; jj++) acc[ii][jj] = fmaf(a[ii], b[jj], acc[ii][jj]);
        }
    }
    __syncthreads();                        // reuse buf as ms[100][101]
#pragma unroll
    for (int ii = 0; ii < 7; ii++){
        int i = ty + 16*ii;
        if (i < 100){
#pragma unroll
            for (int jj = 0; jj < 7; jj++){
                int j = tx + 16*jj;
                if (j < 100) buf[i*101 + j] = acc[ii][jj];
            }
        }
    }
    __syncthreads();
    int w = tid >> 5, lane = tid & 31;
    for (int r = w; r < 100; r += 8){
        float v0 = buf[r*101 + lane];
        float v1 = buf[r*101 + 32 + lane];
        float v2 = buf[r*101 + 64 + lane];
        float v3 = (lane < 4) ? buf[r*101 + 96 + lane] : -1e30f;
        float M = warpMax(fmaxf(fmaxf(v0, v1), fmaxf(v2, v3)));
        float p0 = __expf(v0 - M), p1 = __expf(v1 - M), p2 = __expf(v2 - M);
        float p3 = (lane < 4) ? __expf(v3 - M) : 0.f;
        float S = warpSum(p0 + p1 + p2 + p3);
        float inv = 1.f / S;
        float* o = wr + (size_t)lb*10000 + r*100;
        o[lane] = p0*inv; o[32 + lane] = p1*inv; o[64 + lane] = p2*inv;
        if (lane < 4) o[96 + lane] = p3*inv;
    }
    for (int cc = w; cc < 100; cc += 8){
        float v0 = buf[lane*101 + cc];
        float v1 = buf[(32 + lane)*101 + cc];
        float v2 = buf[(64 + lane)*101 + cc];
        float v3 = (lane < 4) ? buf[(96 + lane)*101 + cc] : -1e30f;
        float M = warpMax(fmaxf(fmaxf(v0, v1), fmaxf(v2, v3)));
        float p0 = __expf(v0 - M), p1 = __expf(v1 - M), p2 = __expf(v2 - M);
        float p3 = (lane < 4) ? __expf(v3 - M) : 0.f;
        float S = warpSum(p0 + p1 + p2 + p3);
        float inv = 1.f / S;
        float* o = wc + (size_t)lb*10000 + cc;
        o[lane*100] = p0*inv; o[(32 + lane)*100] = p1*inv; o[(64 + lane)*100] = p2*inv;
        if (lane < 4) o[(96 + lane)*100] = p3*inv;
    }
}

// -------- fuse (4 queries/block): t = qsa+q1+q2+Wr@q2+Wc^T@q1; softmax over c ----
__global__ void __launch_bounds__(256) k_fuse(
    const float* __restrict__ qsa, const float* __restrict__ q12,
    const float* __restrict__ wr, const float* __restrict__ wc,
    __nv_bfloat16* __restrict__ qh, __nv_bfloat16* __restrict__ ql,
    float* __restrict__ outp)
{
    __shared__ float swr[4][100];
    __shared__ float swc[4][100];
    __shared__ float sh[32];
    int i0 = blockIdx.x * 4, lb = blockIdx.y, c = threadIdx.x;
    const float* q1 = q12 + (size_t)lb*25600;
    const float* q2 = q12 + 409600 + (size_t)lb*25600;
    for (int idx = c; idx < 400; idx += 256){
        int ii = idx / 100, j = idx % 100;
        swr[ii][j] = wr[(size_t)lb*10000 + (i0+ii)*100 + j];
        swc[ii][j] = wc[(size_t)lb*10000 + j*100 + (i0+ii)];
    }
    __syncthreads();
    float acc[4];
#pragma unroll
    for (int ii = 0; ii < 4; ii++)
        acc[ii] = qsa[(size_t)(lb*100 + i0+ii)*256 + c]
                + q1[(size_t)(i0+ii)*256 + c] + q2[(size_t)(i0+ii)*256 + c];
    for (int j = 0; j < 100; j++){
        float q1v = q1[(size_t)j*256 + c];
        float q2v = q2[(size_t)j*256 + c];
#pragma unroll
        for (int ii = 0; ii < 4; ii++){
            acc[ii] = fmaf(swr[ii][j], q2v, acc[ii]);
            acc[ii] = fmaf(swc[ii][j], q1v, acc[ii]);
        }
    }
#pragma unroll
    for (int ii = 0; ii < 4; ii++){
        float M = blockMax(acc[ii], sh);
        float e = __expf(acc[ii] - M);
        float S = blockSum(e, sh);
        float val = e / S;
        size_t off = (size_t)(lb*100 + i0+ii)*256 + c;
        if (outp) outp[off] = val;
        else      hilo(val, &qh[off], &ql[off]);
    }
}

// ---------------- host ----------------
extern "C" void kernel_launch(void* const* d_in, const int* in_sizes, int n_in,
                              void* d_out, int out_size)
{
    float* arena;   cudaGetSymbolAddress((void**)&arena, g_buf);
    float* kvbuf;   cudaGetSymbolAddress((void**)&kvbuf, g_kv);
    __nv_bfloat16 *ahi, *alo, *whi, *wlo;
    cudaGetSymbolAddress((void**)&ahi, g_ahi);
    cudaGetSymbolAddress((void**)&alo, g_alo);
    cudaGetSymbolAddress((void**)&whi, g_whi);
    cudaGetSymbolAddress((void**)&wlo, g_wlo);
    float* bkv;     cudaGetSymbolAddress((void**)&bkv, g_bkv);
    __nv_bfloat16 *qh, *ql, *oh, *ol, *xh, *xl, *och, *ocl;
    cudaGetSymbolAddress((void**)&qh, g_qh);   cudaGetSymbolAddress((void**)&ql, g_ql);
    cudaGetSymbolAddress((void**)&oh, g_oh);   cudaGetSymbolAddress((void**)&ol, g_ol);
    cudaGetSymbolAddress((void**)&xh, g_xh);   cudaGetSymbolAddress((void**)&xl, g_xl);
    cudaGetSymbolAddress((void**)&och, g_och); cudaGetSymbolAddress((void**)&ocl, g_ocl);
    __nv_bfloat16 *wqkvh, *wqkvl, *wswh, *wswl, *wqh, *wql, *wph, *wpl;
    cudaGetSymbolAddress((void**)&wqkvh, g_wqkvh); cudaGetSymbolAddress((void**)&wqkvl, g_wqkvl);
    cudaGetSymbolAddress((void**)&wswh, g_wswh);   cudaGetSymbolAddress((void**)&wswl, g_wswl);
    cudaGetSymbolAddress((void**)&wqh, g_wqh);     cudaGetSymbolAddress((void**)&wql, g_wql);
    cudaGetSymbolAddress((void**)&wph, g_wph);     cudaGetSymbolAddress((void**)&wpl, g_wpl);
    float *bsw, *bwq, *bwp;
    cudaGetSymbolAddress((void**)&bsw, g_bsw);
    cudaGetSymbolAddress((void**)&bwq, g_bwq);
    cudaGetSymbolAddress((void**)&bwp, g_bwp);

    float* qkv  = arena;                 // 1,277,952 (1664*768)
    float* qsa  = arena + 1277952;       // 425,984
    float* qn   = arena + 1703936;       // 425,984
    float* q12  = arena + 2129920;       // 819,200
    float* wr   = arena + 2949120;       // 160,000
    float* wc   = arena + 3109120;       // 160,000
    float* pm   = arena + 3269120;       // 140,800
    float* ps   = arena + 3409920;       // 140,800
    float* pacc = arena + 3550720;       // 4,505,600

    FeatPtrs fp;
    for (int i = 0; i < 8; i++) fp.p[i] = (const float*)d_in[i];
    const float* qe   = (const float*)d_in[8];
    const float* ng   = (const float*)d_in[9];
    const float* nb   = (const float*)d_in[10];
    const float* wq   = (const float*)d_in[11];
    const float* wk   = (const float*)d_in[12];
    const float* wv   = (const float*)d_in[13];
    const float* wp   = (const float*)d_in[14];
    const float* bp   = (const float*)d_in[15];
    const float* wqkv = (const float*)d_in[16];
    const float* swp  = (const float*)d_in[17];
    const float* sbp  = (const float*)d_in[18];

    cudaFuncSetAttribute(k_kvgemm, cudaFuncAttributeMaxDynamicSharedMemorySize, 131072);
    cudaFuncSetAttribute(k_qgemm,  cudaFuncAttributeMaxDynamicSharedMemorySize, 131072);

    k_init_q<<<1600, 256>>>(qe, qh, ql);
    k_tok_ln<<<dim3(680, 2), 256>>>(fp, ahi, alo);
    k_prep_wt<<<dim3(3, 6), 256>>>(wqkv, nullptr, nullptr, nullptr,
                                   wqkvh, wqkvl, nullptr, 768);
    k_qgemm<<<dim3(13, 6), 256, 131072>>>(qh, ql, wqkvh, wqkvl,
                                          nullptr, qkv, 768);   // d=0, profiled slot
    k_prep_w<<<12, 256>>>(wk, wv, ng, nb, whi, wlo, bkv);
    k_kvgemm<<<dim3(340, 2, 12), 512, 131072>>>(ahi, alo, whi, wlo, bkv, kvbuf);
    k_prep_wt<<<dim3(1, 6), 256>>>(swp, nullptr, nullptr, sbp, wswh, wswl, bsw, 256);
    k_prep_wt<<<dim3(1, 6), 256>>>(wq, ng, nb, nullptr, wqh, wql, bwq, 256);
    k_prep_wt<<<dim3(1, 6), 256>>>(wp, nullptr, nullptr, bp, wph, wpl, bwp, 256);

    for (int d = 0; d < 6; d++){
        if (d > 0)
            k_qgemm<<<dim3(13, 6), 256, 131072>>>(qh, ql,
                wqkvh + (size_t)d*768*256, wqkvl + (size_t)d*768*256,
                nullptr, qkv, 768);
        k_sa<<<dim3(8, 4, 4), 128>>>(qkv, oh, ol);
        k_qgemm<<<dim3(13, 2), 256, 131072>>>(oh, ol,
            wswh + (size_t)d*65536, wswl + (size_t)d*65536,
            bsw + d*256, qsa, 256);
        k_lnsplit<<<1600, 256>>>(qsa, xh, xl);
        k_qgemm<<<dim3(13, 2), 256, 131072>>>(xh, xl,
            wqh + (size_t)d*65536, wql + (size_t)d*65536,
            bwq + d*256, qn, 256);
        k_cross<<<dim3(22, 8, 8), 128>>>(qn, kvbuf + (size_t)(2*d)*KVSZ,
                                         kvbuf + (size_t)(2*d+1)*KVSZ, pm, ps, pacc);
        k_combine<<<dim3(4, 8, 8), 128>>>(pm, ps, pacc, och, ocl);
        k_qgemm<<<dim3(25, 2), 256, 131072>>>(och, ocl,
            wph + (size_t)d*65536, wpl + (size_t)d*65536,
            bwp + d*256, q12, 256);
        k_matchsm<<<16, 256, 10100*sizeof(float)>>>(q12, wr, wc);
        k_fuse<<<dim3(25, 16), 256>>>(qsa, q12, wr, wc, qh, ql,
                                      (d == 5) ? (float*)d_out : nullptr);
    }
}